// round 3
// baseline (speedup 1.0000x reference)
#include <cuda_runtime.h>
#include <math.h>
#include <stddef.h>

// ---------------------------------------------------------------------------
// Problem constants
// ---------------------------------------------------------------------------
#define Bn   16
#define NT   1025            // tokens (1 cls + 1024 patches)
#define Cd   768
#define Hh   12
#define Dd   64
#define NP   1024            // patch tokens
#define Ll   256             // landmarks (16x16)
#define BH   (Bn*Hh)         // 192
#define NEWTON_ITERS 6
#define NEG_INV_TAU (-0.125f)   // tau = sqrt(64) = 8

// ---------------------------------------------------------------------------
// Scratch (static device globals)
// ---------------------------------------------------------------------------
__device__ float g_q[BH * NT * Dd];
__device__ float g_k[BH * NT * Dd];
__device__ float g_v[BH * NT * Dd];
__device__ float g_qland[BH * Ll * Dd];
__device__ float g_kland[BH * Ll * Dd];
__device__ float g_qpn[BH * NP];
__device__ float g_kpn[BH * NP];
__device__ float g_qln[BH * Ll];
__device__ float g_kln[BH * Ll];
__device__ float g_qcn[BH];
__device__ float g_M1[(size_t)BH * NP * Ll];
__device__ float g_M2[(size_t)BH * Ll * Ll];
__device__ float g_M3[(size_t)BH * Ll * NP];
__device__ float g_invA[(size_t)BH * Ll * Ll];
__device__ float g_invB[(size_t)BH * Ll * Ll];
__device__ float g_T[(size_t)BH * Ll * Ll];
__device__ float g_KV[BH * Ll * Dd];
__device__ float g_Vmix[BH * Ll * Dd];
__device__ float g_attn[(size_t)Bn * NT * Cd];

// ---------------------------------------------------------------------------
// Epilogue functors
// ---------------------------------------------------------------------------
struct EpiQKV {
    const float* bias;
    __device__ __forceinline__ void store(int, int m, int j, float acc) const {
        int b = m / NT, n = m % NT;
        int part = j / Cd;
        int rem  = j % Cd;
        int h = rem / Dd, d = rem % Dd;
        float* dst = (part == 0) ? g_q : ((part == 1) ? g_k : g_v);
        dst[(((size_t)b * Hh + h) * NT + n) * Dd + d] = acc + bias[j];
    }
};

struct EpiGauss {
    const float* xn; const float* yn; float* out;
    int sxn; int syn; int ldc; size_t sout;
    __device__ __forceinline__ void store(int bh, int m, int n, float acc) const {
        float dist = xn[(size_t)bh * sxn + m] + yn[(size_t)bh * syn + n] - 2.0f * acc;
        out[(size_t)bh * sout + (size_t)m * ldc + n] = expf(dist * NEG_INV_TAU);
    }
};

struct EpiPlain {
    float* out; int ldc; size_t s;
    __device__ __forceinline__ void store(int bh, int m, int n, float acc) const {
        out[(size_t)bh * s + (size_t)m * ldc + n] = acc;
    }
};

struct EpiNewton {   // out = 2*inv - acc
    const float* inv; float* out;
    __device__ __forceinline__ void store(int bh, int m, int n, float acc) const {
        size_t off = ((size_t)bh * Ll + m) * Ll + n;
        out[off] = 2.0f * inv[off] - acc;
    }
};

struct EpiYPatch {
    __device__ __forceinline__ void store(int bh, int m, int j, float acc) const {
        int b = bh / Hh, h = bh % Hh;
        g_attn[((size_t)b * NT + (m + 1)) * Cd + h * Dd + j] = acc;
    }
};

struct EpiProj {
    const float* bias; float* out;
    __device__ __forceinline__ void store(int, int m, int j, float acc) const {
        out[(size_t)m * Cd + j] = acc + bias[j];
    }
};

// ---------------------------------------------------------------------------
// TF32 / cp.async helpers
// ---------------------------------------------------------------------------
__device__ __forceinline__ unsigned f2t(float f) {
    unsigned u;
    asm("cvt.rna.tf32.f32 %0, %1;" : "=r"(u) : "f"(f));
    return u;
}

__device__ __forceinline__ void mma_tf32(float* c, const unsigned* a, const unsigned* b) {
    asm volatile(
        "mma.sync.aligned.m16n8k8.row.col.f32.tf32.tf32.f32 "
        "{%0,%1,%2,%3}, {%4,%5,%6,%7}, {%8,%9}, {%0,%1,%2,%3};"
        : "+f"(c[0]), "+f"(c[1]), "+f"(c[2]), "+f"(c[3])
        : "r"(a[0]), "r"(a[1]), "r"(a[2]), "r"(a[3]), "r"(b[0]), "r"(b[1]));
}

__device__ __forceinline__ void cpa16(void* dst, const void* src, bool valid) {
    unsigned d = (unsigned)__cvta_generic_to_shared(dst);
    int sz = valid ? 16 : 0;
    asm volatile("cp.async.cg.shared.global [%0], [%1], 16, %2;"
                 :: "r"(d), "l"(src), "r"(sz));
}
#define CP_COMMIT() asm volatile("cp.async.commit_group;")
#define CP_WAIT0()  asm volatile("cp.async.wait_group 0;" ::: "memory")

// ---------------------------------------------------------------------------
// Pipelined TF32 tensor-core GEMM.  C = A(MxK, row-major, lda) @ op(B)
//   BT=true : B is [N x K] row-major (C = A @ B^T)
//   BT=false: B is [K x N] row-major (C = A @ B)
// 2-stage cp.async double buffering; smem holds raw fp32, cvt at frag load.
// Requires: K % 32 == 0, Nn % BN == 0, lda/ldb % 4 == 0. M may be ragged.
// ---------------------------------------------------------------------------
template<int BM, int BN, bool BT>
struct GemmCfg {
    static constexpr int BK = 32;
    static constexpr int WARPS_M = BM / 64;
    static constexpr int WARPS_N = BN / 32;
    static constexpr int THREADS = WARPS_M * WARPS_N * 32;
    static constexpr int SA  = BK + 4;                      // A row stride (floats)
    static constexpr int SB  = BT ? (BK + 4) : (BN + 8);    // B row stride
    static constexpr int ASZ = BM * SA;                     // per stage
    static constexpr int BSZ = BT ? (BN * SA) : (BK * SB);
    static constexpr int SMEM_BYTES = (2 * ASZ + 2 * BSZ) * 4;
};

template<int BM, int BN, bool BT, class Epi>
__global__ void __launch_bounds__(GemmCfg<BM,BN,BT>::THREADS)
gemm_tc(const float* __restrict__ A, const float* __restrict__ Bp,
        int M, int Nn, int K, int lda, int ldb,
        size_t sA, size_t sB, Epi epi)
{
    using C = GemmCfg<BM, BN, BT>;
    constexpr int BK = C::BK;
    constexpr int THREADS = C::THREADS;
    constexpr int SA = C::SA;
    constexpr int SBs = C::SB;

    extern __shared__ float smem[];
    float* As = smem;                 // 2 stages of [BM][SA]
    float* Bs = smem + 2 * C::ASZ;    // 2 stages

    const int bh = blockIdx.z;
    A  += (size_t)bh * sA;
    Bp += (size_t)bh * sB;
    const int m0 = blockIdx.y * BM;
    const int n0 = blockIdx.x * BN;
    const int tid  = threadIdx.x;
    const int lane = tid & 31;
    const int warp = tid >> 5;
    const int wm = warp / C::WARPS_N;
    const int wn = warp % C::WARPS_N;
    const int gid = lane >> 2;      // 0..7
    const int tig = lane & 3;       // 0..3

    float acc[4][4][4];
#pragma unroll
    for (int i = 0; i < 4; i++)
#pragma unroll
        for (int j = 0; j < 4; j++)
#pragma unroll
            for (int r = 0; r < 4; r++) acc[i][j][r] = 0.0f;

    // ---- async tile loader ----
    auto load_tile = [&](int k0, int s) {
        float* Asb = As + s * C::ASZ;
        float* Bsb = Bs + s * C::BSZ;
        // A: [BM][BK] from row-major A
#pragma unroll
        for (int t = 0; t < (BM * BK / 4) / THREADS; t++) {
            int i  = tid + t * THREADS;
            int m  = i >> 3;             // BK/4 = 8 quads per row
            int kq = i & 7;
            bool v = (m0 + m < M);
            const float* src = A + (size_t)(v ? (m0 + m) : m0) * lda + k0 + kq * 4;
            cpa16(&Asb[m * SA + kq * 4], src, v);
        }
        if (BT) {   // B [N x K] -> Bs[n][k]
#pragma unroll
            for (int t = 0; t < (BN * BK / 4) / THREADS; t++) {
                int i  = tid + t * THREADS;
                int n  = i >> 3;
                int kq = i & 7;
                const float* src = Bp + (size_t)(n0 + n) * ldb + k0 + kq * 4;
                cpa16(&Bsb[n * SA + kq * 4], src, true);
            }
        } else {    // B [K x N] -> Bs[k][n]
#pragma unroll
            for (int t = 0; t < (BK * BN / 4) / THREADS; t++) {
                int i  = tid + t * THREADS;
                int kk = i / (BN / 4);
                int nq = i % (BN / 4);
                const float* src = Bp + (size_t)(k0 + kk) * ldb + n0 + nq * 4;
                cpa16(&Bsb[kk * SBs + nq * 4], src, true);
            }
        }
        CP_COMMIT();
    };

    const int nk = K / BK;
    load_tile(0, 0);

    for (int it = 0; it < nk; it++) {
        const int s = it & 1;
        CP_WAIT0();
        __syncthreads();
        if (it + 1 < nk) load_tile((it + 1) * BK, s ^ 1);

        const float* Asb = As + s * C::ASZ;
        const float* Bsb = Bs + s * C::BSZ;
#pragma unroll
        for (int kk = 0; kk < BK; kk += 8) {
            unsigned af[4][4], bf[4][2];
#pragma unroll
            for (int i = 0; i < 4; i++) {
                int r0 = wm * 64 + i * 16 + gid;
                af[i][0] = f2t(Asb[r0 * SA + kk + tig]);
                af[i][1] = f2t(Asb[(r0 + 8) * SA + kk + tig]);
                af[i][2] = f2t(Asb[r0 * SA + kk + tig + 4]);
                af[i][3] = f2t(Asb[(r0 + 8) * SA + kk + tig + 4]);
            }
#pragma unroll
            for (int j = 0; j < 4; j++) {
                int c0 = wn * 32 + j * 8 + gid;
                if (BT) {
                    bf[j][0] = f2t(Bsb[c0 * SA + kk + tig]);
                    bf[j][1] = f2t(Bsb[c0 * SA + kk + tig + 4]);
                } else {
                    bf[j][0] = f2t(Bsb[(kk + tig) * SBs + c0]);
                    bf[j][1] = f2t(Bsb[(kk + tig + 4) * SBs + c0]);
                }
            }
#pragma unroll
            for (int i = 0; i < 4; i++)
#pragma unroll
                for (int j = 0; j < 4; j++)
                    mma_tf32(acc[i][j], af[i], bf[j]);
        }
        __syncthreads();
    }

    // ---- epilogue (N exact multiple of BN; only M ragged) ----
#pragma unroll
    for (int i = 0; i < 4; i++) {
        int rm = m0 + wm * 64 + i * 16 + gid;
#pragma unroll
        for (int j = 0; j < 4; j++) {
            int cn = n0 + wn * 32 + j * 8 + tig * 2;
            if (rm < M) {
                epi.store(bh, rm, cn,     acc[i][j][0]);
                epi.store(bh, rm, cn + 1, acc[i][j][1]);
            }
            if (rm + 8 < M) {
                epi.store(bh, rm + 8, cn,     acc[i][j][2]);
                epi.store(bh, rm + 8, cn + 1, acc[i][j][3]);
            }
        }
    }
}

// ---------------------------------------------------------------------------
// Small helper kernels
// ---------------------------------------------------------------------------
__global__ void pool_kernel()
{
    int idx = blockIdx.x * blockDim.x + threadIdx.x;
    if (idx >= BH * Ll * Dd) return;
    int d  = idx % Dd;
    int l  = (idx / Dd) % Ll;
    int bh = idx / (Dd * Ll);
    int lr = l / 16, lc = l % 16;
    float sq = 0.f, sk = 0.f;
#pragma unroll
    for (int r = 0; r < 2; r++)
#pragma unroll
        for (int c = 0; c < 2; c++) {
            int p = (2 * lr + r) * 32 + (2 * lc + c);
            size_t off = ((size_t)bh * NT + (p + 1)) * Dd + d;
            sq += g_q[off];
            sk += g_k[off];
        }
    g_qland[((size_t)bh * Ll + l) * Dd + d] = sq * 0.25f;
    g_kland[((size_t)bh * Ll + l) * Dd + d] = sk * 0.25f;
}

__device__ __forceinline__ float row_sq_norm(const float* p)
{
    const float4* p4 = (const float4*)p;
    float s = 0.f;
#pragma unroll
    for (int i = 0; i < Dd / 4; i++) {
        float4 v = p4[i];
        s += v.x * v.x + v.y * v.y + v.z * v.z + v.w * v.w;
    }
    return s;
}

__global__ void norms_patch_kernel()
{
    int idx = blockIdx.x * blockDim.x + threadIdx.x;
    if (idx >= BH * NP) return;
    int bh = idx / NP, p = idx % NP;
    size_t off = ((size_t)bh * NT + (p + 1)) * Dd;
    g_qpn[idx] = row_sq_norm(&g_q[off]);
    g_kpn[idx] = row_sq_norm(&g_k[off]);
}

__global__ void norms_land_kernel()
{
    int idx = blockIdx.x * blockDim.x + threadIdx.x;
    if (idx >= BH * Ll) return;
    g_qln[idx] = row_sq_norm(&g_qland[(size_t)idx * Dd]);
    g_kln[idx] = row_sq_norm(&g_kland[(size_t)idx * Dd]);
    if (idx < BH)
        g_qcn[idx] = row_sq_norm(&g_q[(size_t)idx * NT * Dd]);  // n = 0 (cls)
}

__global__ void newton_init_kernel()
{
    int bh = blockIdx.x;
    int t  = threadIdx.x;        // 256 threads, one row each
    const float* M2b = g_M2 + (size_t)bh * Ll * Ll;
    const float* row = M2b + (size_t)t * Ll;
    float rs = 0.f;
    for (int j = 0; j < Ll; j++) rs += fabsf(row[j]);
    __shared__ float red[256];
    red[t] = rs;
    __syncthreads();
    for (int s = 128; s > 0; s >>= 1) {
        if (t < s) red[t] = fmaxf(red[t], red[t + s]);
        __syncthreads();
    }
    float nrm = red[0];
    float scale = 1.0f / (nrm * nrm + 1e-6f);
    float* inv = g_invA + (size_t)bh * Ll * Ll;
    for (int idx = t; idx < Ll * Ll; idx += 256) {
        int i = idx / Ll, j = idx % Ll;
        inv[idx] = M2b[(size_t)j * Ll + i] * scale;
    }
}

__global__ void ycls_kernel()
{
    int bh = blockIdx.x;
    int t  = threadIdx.x;        // 256 threads
    __shared__ float sc[Ll];
    __shared__ float qc[Dd];
    if (t < Dd) qc[t] = g_q[(size_t)bh * NT * Dd + t];
    __syncthreads();
    const float* kl = g_kland + ((size_t)bh * Ll + t) * Dd;
    float dot = 0.f;
#pragma unroll
    for (int d = 0; d < Dd; d++) dot += qc[d] * kl[d];
    float dist = g_qcn[bh] + g_kln[(size_t)bh * Ll + t] - 2.0f * dot;
    sc[t] = expf(dist * NEG_INV_TAU);
    __syncthreads();
    if (t < Dd) {
        float s = 0.f;
        for (int l = 0; l < Ll; l++)
            s += sc[l] * g_Vmix[((size_t)bh * Ll + l) * Dd + t];
        int b = bh / Hh, h = bh % Hh;
        g_attn[(size_t)b * NT * Cd + h * Dd + t] = s;
    }
}

// ---------------------------------------------------------------------------
// Host launcher
// ---------------------------------------------------------------------------
template<int BM, int BN, bool BT, class Epi>
static void launch_gemm(dim3 grid, const float* A, const float* Bp,
                        int M, int Nn, int K, int lda, int ldb,
                        size_t sA, size_t sB, Epi epi)
{
    using C = GemmCfg<BM, BN, BT>;
    static bool attr_done = false;
    if (!attr_done) {
        cudaFuncSetAttribute((const void*)gemm_tc<BM, BN, BT, Epi>,
                             cudaFuncAttributeMaxDynamicSharedMemorySize,
                             C::SMEM_BYTES);
        attr_done = true;
    }
    gemm_tc<BM, BN, BT, Epi><<<grid, C::THREADS, C::SMEM_BYTES>>>(
        A, Bp, M, Nn, K, lda, ldb, sA, sB, epi);
}

extern "C" void kernel_launch(void* const* d_in, const int* in_sizes, int n_in,
                              void* d_out, int out_size)
{
    (void)in_sizes; (void)n_in; (void)out_size;
    const float* x      = (const float*)d_in[0];
    const float* qkv_w  = (const float*)d_in[1];
    const float* qkv_b  = (const float*)d_in[2];
    const float* proj_w = (const float*)d_in[3];
    const float* proj_b = (const float*)d_in[4];
    float* out = (float*)d_out;

    float *p_q, *p_k, *p_v, *p_qland, *p_kland;
    float *p_qpn, *p_kpn, *p_qln, *p_kln;
    float *p_M1, *p_M2, *p_M3, *p_invA, *p_invB, *p_T, *p_KV, *p_Vmix, *p_attn;
    cudaGetSymbolAddress((void**)&p_q, g_q);
    cudaGetSymbolAddress((void**)&p_k, g_k);
    cudaGetSymbolAddress((void**)&p_v, g_v);
    cudaGetSymbolAddress((void**)&p_qland, g_qland);
    cudaGetSymbolAddress((void**)&p_kland, g_kland);
    cudaGetSymbolAddress((void**)&p_qpn, g_qpn);
    cudaGetSymbolAddress((void**)&p_kpn, g_kpn);
    cudaGetSymbolAddress((void**)&p_qln, g_qln);
    cudaGetSymbolAddress((void**)&p_kln, g_kln);
    cudaGetSymbolAddress((void**)&p_M1, g_M1);
    cudaGetSymbolAddress((void**)&p_M2, g_M2);
    cudaGetSymbolAddress((void**)&p_M3, g_M3);
    cudaGetSymbolAddress((void**)&p_invA, g_invA);
    cudaGetSymbolAddress((void**)&p_invB, g_invB);
    cudaGetSymbolAddress((void**)&p_T, g_T);
    cudaGetSymbolAddress((void**)&p_KV, g_KV);
    cudaGetSymbolAddress((void**)&p_Vmix, g_Vmix);
    cudaGetSymbolAddress((void**)&p_attn, g_attn);

    const int M_tok = Bn * NT;   // 16400
    const int gy_tok = (M_tok + 127) / 128;

    // 1. QKV projection: x @ qkv_w^T + b, scattered into q/k/v [B][H][N][D]
    launch_gemm<128, 128, true>(dim3(3 * Cd / 128, gy_tok, 1),
        x, qkv_w, M_tok, 3 * Cd, Cd, Cd, Cd, 0, 0, EpiQKV{qkv_b});

    // 2. pooling + norms
    pool_kernel<<<(BH * Ll * Dd + 255) / 256, 256>>>();
    norms_patch_kernel<<<(BH * NP + 255) / 256, 256>>>();
    norms_land_kernel<<<(BH * Ll + 255) / 256, 256>>>();

    // 3. Gauss kernel matrices
    launch_gemm<128, 128, true>(dim3(Ll / 128, Ll / 128, BH),       // M2
        p_qland, p_kland, Ll, Ll, Dd, Dd, Dd,
        (size_t)Ll * Dd, (size_t)Ll * Dd,
        EpiGauss{p_qln, p_kln, p_M2, Ll, Ll, Ll, (size_t)Ll * Ll});
    launch_gemm<128, 128, true>(dim3(Ll / 128, NP / 128, BH),       // M1
        p_q + Dd, p_kland, NP, Ll, Dd, Dd, Dd,
        (size_t)NT * Dd, (size_t)Ll * Dd,
        EpiGauss{p_qpn, p_kln, p_M1, NP, Ll, Ll, (size_t)NP * Ll});
    launch_gemm<128, 128, true>(dim3(NP / 128, Ll / 128, BH),       // M3
        p_qland, p_k + Dd, Ll, NP, Dd, Dd, Dd,
        (size_t)Ll * Dd, (size_t)NT * Dd,
        EpiGauss{p_qln, p_kpn, p_M3, Ll, NP, NP, (size_t)Ll * NP});

    // 4. Newton iterations for M2^-1
    newton_init_kernel<<<BH, 256>>>();
    {
        float* cur = p_invA;
        float* nxt = p_invB;
        dim3 grid(Ll / 128, Ll / 128, BH);
        for (int it = 0; it < NEWTON_ITERS; it++) {
            launch_gemm<128, 128, false>(grid,
                p_M2, cur, Ll, Ll, Ll, Ll, Ll,
                (size_t)Ll * Ll, (size_t)Ll * Ll,
                EpiPlain{p_T, Ll, (size_t)Ll * Ll});
            launch_gemm<128, 128, false>(grid,
                cur, p_T, Ll, Ll, Ll, Ll, Ll,
                (size_t)Ll * Ll, (size_t)Ll * Ll,
                EpiNewton{cur, nxt});
            float* tmp = cur; cur = nxt; nxt = tmp;
        }
        // NEWTON_ITERS even -> result in p_invA
    }

    // 5. KV = M3 @ v_patch : [L x D]
    launch_gemm<128, 64, false>(dim3(1, Ll / 128, BH),
        p_M3, p_v + Dd, Ll, Dd, NP, NP, Dd,
        (size_t)Ll * NP, (size_t)NT * Dd,
        EpiPlain{p_KV, Dd, (size_t)Ll * Dd});
    // 6. V_mixed = M2_inv @ KV : [L x D]
    launch_gemm<128, 64, false>(dim3(1, Ll / 128, BH),
        p_invA, p_KV, Ll, Dd, Ll, Ll, Dd,
        (size_t)Ll * Ll, (size_t)Ll * Dd,
        EpiPlain{p_Vmix, Dd, (size_t)Ll * Dd});
    // 7. y_patch = M1 @ V_mixed -> attn[b][1..1024][h*64+d]
    launch_gemm<128, 64, false>(dim3(1, NP / 128, BH),
        p_M1, p_Vmix, NP, Dd, Ll, Ll, Dd,
        (size_t)NP * Ll, (size_t)Ll * Dd, EpiYPatch{});
    // 8. y_cls -> attn[b][0][h*64+d]
    ycls_kernel<<<BH, 256>>>();

    // 9. output projection: attn @ proj_w^T + proj_b
    launch_gemm<128, 128, true>(dim3(Cd / 128, gy_tok, 1),
        p_attn, proj_w, M_tok, Cd, Cd, Cd, Cd, 0, 0, EpiProj{proj_b, out});
}

// round 4
// speedup vs baseline: 1.1309x; 1.1309x over previous
#include <cuda_runtime.h>
#include <math.h>
#include <stddef.h>

// ---------------------------------------------------------------------------
// Problem constants
// ---------------------------------------------------------------------------
#define Bn   16
#define NT   1025            // tokens (1 cls + 1024 patches)
#define Cd   768
#define Hh   12
#define Dd   64
#define NP   1024            // patch tokens
#define Ll   256             // landmarks (16x16)
#define BH   (Bn*Hh)         // 192
#define NEWTON_ITERS 6
#define NEG_INV_TAU (-0.125f)   // tau = sqrt(64) = 8

// ---------------------------------------------------------------------------
// Scratch (static device globals)
// ---------------------------------------------------------------------------
__device__ float g_q[BH * NT * Dd];
__device__ float g_k[BH * NT * Dd];
__device__ float g_v[BH * NT * Dd];
__device__ float g_qland[BH * Ll * Dd];
__device__ float g_kland[BH * Ll * Dd];
__device__ float g_qpn[BH * NP];
__device__ float g_kpn[BH * NP];
__device__ float g_qln[BH * Ll];
__device__ float g_kln[BH * Ll];
__device__ float g_qcn[BH];
__device__ float g_M1[(size_t)BH * NP * Ll];
__device__ float g_M2[(size_t)BH * Ll * Ll];
__device__ float g_M3[(size_t)BH * Ll * NP];
__device__ float g_invA[(size_t)BH * Ll * Ll];
__device__ float g_invB[(size_t)BH * Ll * Ll];
__device__ float g_T[(size_t)BH * Ll * Ll];
__device__ float g_KV[BH * Ll * Dd];
__device__ float g_Vmix[BH * Ll * Dd];
__device__ float g_attn[(size_t)Bn * NT * Cd];

// ---------------------------------------------------------------------------
// Epilogue functors
// ---------------------------------------------------------------------------
struct EpiQKV {
    const float* bias;
    __device__ __forceinline__ void store(int, int m, int j, float acc) const {
        int b = m / NT, n = m % NT;
        int part = j / Cd;
        int rem  = j % Cd;
        int h = rem / Dd, d = rem % Dd;
        float* dst = (part == 0) ? g_q : ((part == 1) ? g_k : g_v);
        dst[(((size_t)b * Hh + h) * NT + n) * Dd + d] = acc + bias[j];
    }
};

struct EpiGauss {
    const float* xn; const float* yn; float* out;
    int sxn; int syn; int ldc; size_t sout;
    __device__ __forceinline__ void store(int bh, int m, int n, float acc) const {
        float dist = xn[(size_t)bh * sxn + m] + yn[(size_t)bh * syn + n] - 2.0f * acc;
        out[(size_t)bh * sout + (size_t)m * ldc + n] = expf(dist * NEG_INV_TAU);
    }
};

struct EpiPlain {
    float* out; int ldc; size_t s;
    __device__ __forceinline__ void store(int bh, int m, int n, float acc) const {
        out[(size_t)bh * s + (size_t)m * ldc + n] = acc;
    }
};

struct EpiNewton {   // out = 2*inv - acc
    const float* inv; float* out;
    __device__ __forceinline__ void store(int bh, int m, int n, float acc) const {
        size_t off = ((size_t)bh * Ll + m) * Ll + n;
        out[off] = 2.0f * inv[off] - acc;
    }
};

struct EpiYPatch {
    __device__ __forceinline__ void store(int bh, int m, int j, float acc) const {
        int b = bh / Hh, h = bh % Hh;
        g_attn[((size_t)b * NT + (m + 1)) * Cd + h * Dd + j] = acc;
    }
};

struct EpiProj {
    const float* bias; float* out;
    __device__ __forceinline__ void store(int, int m, int j, float acc) const {
        out[(size_t)m * Cd + j] = acc + bias[j];
    }
};

// ---------------------------------------------------------------------------
// TF32 helpers
// ---------------------------------------------------------------------------
__device__ __forceinline__ unsigned f2t(float f) {
    unsigned u;
    asm("cvt.rna.tf32.f32 %0, %1;" : "=r"(u) : "f"(f));
    return u;
}

__device__ __forceinline__ void mma_tf32(float* c, const unsigned* a, const unsigned* b) {
    asm volatile(
        "mma.sync.aligned.m16n8k8.row.col.f32.tf32.tf32.f32 "
        "{%0,%1,%2,%3}, {%4,%5,%6,%7}, {%8,%9}, {%0,%1,%2,%3};"
        : "+f"(c[0]), "+f"(c[1]), "+f"(c[2]), "+f"(c[3])
        : "r"(a[0]), "r"(a[1]), "r"(a[2]), "r"(a[3]), "r"(b[0]), "r"(b[1]));
}

// ---------------------------------------------------------------------------
// Register-staged, double-buffered TF32 GEMM.  C = A(MxK,row-major,lda) @ op(B)
//   BT=true : B is [N x K] row-major (C = A @ B^T)
//   BT=false: B is [K x N] row-major (C = A @ B)
// smem holds PRE-CONVERTED tf32 (cvt once at store; MMA loop has zero cvt).
// Next k-stage is LDG'd into registers while the current stage computes.
// Requires: K % 32 == 0, Nn % BN == 0, lda/ldb % 4 == 0. M may be ragged.
// ---------------------------------------------------------------------------
template<int BM, int BN, bool BT>
struct GemmCfg {
    static constexpr int BK = 32;
    static constexpr int WARPS_M = BM / 64;
    static constexpr int WARPS_N = BN / 32;
    static constexpr int THREADS = WARPS_M * WARPS_N * 32;
    static constexpr int SA  = BK + 4;                      // A/B(BT) row stride
    static constexpr int SB  = BT ? (BK + 4) : (BN + 8);    // B row stride
    static constexpr int ASZ = BM * SA;                     // per stage (u32)
    static constexpr int BSZ = BT ? (BN * SA) : (BK * SB);
    static constexpr int AQ  = (BM * BK / 4) / THREADS;     // float4 per thread
    static constexpr int BQ  = (BT ? (BN * BK / 4) : (BK * BN / 4)) / THREADS;
    static constexpr int SMEM_BYTES = 2 * (ASZ + BSZ) * 4;
};

template<int BM, int BN, bool BT, class Epi>
__global__ void __launch_bounds__(GemmCfg<BM,BN,BT>::THREADS)
gemm_tc(const float* __restrict__ A, const float* __restrict__ Bp,
        int M, int Nn, int K, int lda, int ldb,
        size_t sA, size_t sB, Epi epi)
{
    using C = GemmCfg<BM, BN, BT>;
    constexpr int BK = C::BK;
    constexpr int THREADS = C::THREADS;
    constexpr int SA = C::SA;
    constexpr int SBs = C::SB;

    extern __shared__ unsigned smem[];
    unsigned* As = smem;                  // 2 stages [BM][SA]
    unsigned* Bs = smem + 2 * C::ASZ;     // 2 stages

    const int bh = blockIdx.z;
    A  += (size_t)bh * sA;
    Bp += (size_t)bh * sB;
    const int m0 = blockIdx.y * BM;
    const int n0 = blockIdx.x * BN;
    const int tid  = threadIdx.x;
    const int lane = tid & 31;
    const int warp = tid >> 5;
    const int wm = warp / C::WARPS_N;
    const int wn = warp % C::WARPS_N;
    const int gid = lane >> 2;      // 0..7
    const int tig = lane & 3;       // 0..3

    float acc[4][4][4];
#pragma unroll
    for (int i = 0; i < 4; i++)
#pragma unroll
        for (int j = 0; j < 4; j++)
#pragma unroll
            for (int r = 0; r < 4; r++) acc[i][j][r] = 0.0f;

    float4 aReg[C::AQ];
    float4 bReg[C::BQ];

    // ---- LDG next tile into registers ----
    auto ldg_tile = [&](int k0) {
#pragma unroll
        for (int t = 0; t < C::AQ; t++) {
            int i  = tid + t * THREADS;
            int m  = i >> 3;            // BK/4 = 8 quads per row
            int kq = i & 7;
            bool v = (m0 + m < M);
            float4 val = *(const float4*)&A[(size_t)(v ? (m0 + m) : m0) * lda + k0 + kq * 4];
            if (!v) val = make_float4(0.f, 0.f, 0.f, 0.f);
            aReg[t] = val;
        }
        if (BT) {
#pragma unroll
            for (int t = 0; t < C::BQ; t++) {
                int i  = tid + t * THREADS;
                int n  = i >> 3;
                int kq = i & 7;
                bReg[t] = *(const float4*)&Bp[(size_t)(n0 + n) * ldb + k0 + kq * 4];
            }
        } else {
#pragma unroll
            for (int t = 0; t < C::BQ; t++) {
                int i  = tid + t * THREADS;
                int kk = i / (BN / 4);
                int nq = i % (BN / 4);
                bReg[t] = *(const float4*)&Bp[(size_t)(k0 + kk) * ldb + n0 + nq * 4];
            }
        }
    };

    // ---- cvt + STS registers into stage s ----
    auto sts_tile = [&](int s) {
        unsigned* Asb = As + s * C::ASZ;
        unsigned* Bsb = Bs + s * C::BSZ;
#pragma unroll
        for (int t = 0; t < C::AQ; t++) {
            int i  = tid + t * THREADS;
            int m  = i >> 3;
            int kq = i & 7;
            float4 v = aReg[t];
            uint4 u = make_uint4(f2t(v.x), f2t(v.y), f2t(v.z), f2t(v.w));
            *(uint4*)&Asb[m * SA + kq * 4] = u;
        }
        if (BT) {
#pragma unroll
            for (int t = 0; t < C::BQ; t++) {
                int i  = tid + t * THREADS;
                int n  = i >> 3;
                int kq = i & 7;
                float4 v = bReg[t];
                uint4 u = make_uint4(f2t(v.x), f2t(v.y), f2t(v.z), f2t(v.w));
                *(uint4*)&Bsb[n * SA + kq * 4] = u;
            }
        } else {
#pragma unroll
            for (int t = 0; t < C::BQ; t++) {
                int i  = tid + t * THREADS;
                int kk = i / (BN / 4);
                int nq = i % (BN / 4);
                float4 v = bReg[t];
                uint4 u = make_uint4(f2t(v.x), f2t(v.y), f2t(v.z), f2t(v.w));
                *(uint4*)&Bsb[kk * SBs + nq * 4] = u;
            }
        }
    };

    const int nk = K / BK;
    ldg_tile(0);
    sts_tile(0);
    __syncthreads();

    for (int it = 0; it < nk; it++) {
        const int s = it & 1;
        if (it + 1 < nk) ldg_tile((it + 1) * BK);   // overlap with compute below

        const unsigned* Asb = As + s * C::ASZ;
        const unsigned* Bsb = Bs + s * C::BSZ;
#pragma unroll
        for (int kk = 0; kk < BK; kk += 8) {
            unsigned af[4][4], bf[4][2];
#pragma unroll
            for (int i = 0; i < 4; i++) {
                int r0 = wm * 64 + i * 16 + gid;
                af[i][0] = Asb[r0 * SA + kk + tig];
                af[i][1] = Asb[(r0 + 8) * SA + kk + tig];
                af[i][2] = Asb[r0 * SA + kk + tig + 4];
                af[i][3] = Asb[(r0 + 8) * SA + kk + tig + 4];
            }
#pragma unroll
            for (int j = 0; j < 4; j++) {
                int c0 = wn * 32 + j * 8 + gid;
                if (BT) {
                    bf[j][0] = Bsb[c0 * SA + kk + tig];
                    bf[j][1] = Bsb[c0 * SA + kk + tig + 4];
                } else {
                    bf[j][0] = Bsb[(kk + tig) * SBs + c0];
                    bf[j][1] = Bsb[(kk + tig + 4) * SBs + c0];
                }
            }
#pragma unroll
            for (int i = 0; i < 4; i++)
#pragma unroll
                for (int j = 0; j < 4; j++)
                    mma_tf32(acc[i][j], af[i], bf[j]);
        }

        if (it + 1 < nk) {
            sts_tile(s ^ 1);       // write other stage (nobody reads it now)
            __syncthreads();       // make visible before next compute
        }
    }

    // ---- epilogue (N exact multiple of BN; only M ragged) ----
#pragma unroll
    for (int i = 0; i < 4; i++) {
        int rm = m0 + wm * 64 + i * 16 + gid;
#pragma unroll
        for (int j = 0; j < 4; j++) {
            int cn = n0 + wn * 32 + j * 8 + tig * 2;
            if (rm < M) {
                epi.store(bh, rm, cn,     acc[i][j][0]);
                epi.store(bh, rm, cn + 1, acc[i][j][1]);
            }
            if (rm + 8 < M) {
                epi.store(bh, rm + 8, cn,     acc[i][j][2]);
                epi.store(bh, rm + 8, cn + 1, acc[i][j][3]);
            }
        }
    }
}

// ---------------------------------------------------------------------------
// Small helper kernels
// ---------------------------------------------------------------------------
__global__ void pool_kernel()
{
    int idx = blockIdx.x * blockDim.x + threadIdx.x;
    if (idx >= BH * Ll * Dd) return;
    int d  = idx % Dd;
    int l  = (idx / Dd) % Ll;
    int bh = idx / (Dd * Ll);
    int lr = l / 16, lc = l % 16;
    float sq = 0.f, sk = 0.f;
#pragma unroll
    for (int r = 0; r < 2; r++)
#pragma unroll
        for (int c = 0; c < 2; c++) {
            int p = (2 * lr + r) * 32 + (2 * lc + c);
            size_t off = ((size_t)bh * NT + (p + 1)) * Dd + d;
            sq += g_q[off];
            sk += g_k[off];
        }
    g_qland[((size_t)bh * Ll + l) * Dd + d] = sq * 0.25f;
    g_kland[((size_t)bh * Ll + l) * Dd + d] = sk * 0.25f;
}

__device__ __forceinline__ float row_sq_norm(const float* p)
{
    const float4* p4 = (const float4*)p;
    float s = 0.f;
#pragma unroll
    for (int i = 0; i < Dd / 4; i++) {
        float4 v = p4[i];
        s += v.x * v.x + v.y * v.y + v.z * v.z + v.w * v.w;
    }
    return s;
}

__global__ void norms_patch_kernel()
{
    int idx = blockIdx.x * blockDim.x + threadIdx.x;
    if (idx >= BH * NP) return;
    int bh = idx / NP, p = idx % NP;
    size_t off = ((size_t)bh * NT + (p + 1)) * Dd;
    g_qpn[idx] = row_sq_norm(&g_q[off]);
    g_kpn[idx] = row_sq_norm(&g_k[off]);
}

__global__ void norms_land_kernel()
{
    int idx = blockIdx.x * blockDim.x + threadIdx.x;
    if (idx >= BH * Ll) return;
    g_qln[idx] = row_sq_norm(&g_qland[(size_t)idx * Dd]);
    g_kln[idx] = row_sq_norm(&g_kland[(size_t)idx * Dd]);
    if (idx < BH)
        g_qcn[idx] = row_sq_norm(&g_q[(size_t)idx * NT * Dd]);  // n = 0 (cls)
}

__global__ void newton_init_kernel()
{
    int bh = blockIdx.x;
    int t  = threadIdx.x;        // 256 threads, one row each
    const float* M2b = g_M2 + (size_t)bh * Ll * Ll;
    const float* row = M2b + (size_t)t * Ll;
    float rs = 0.f;
    for (int j = 0; j < Ll; j++) rs += fabsf(row[j]);
    __shared__ float red[256];
    red[t] = rs;
    __syncthreads();
    for (int s = 128; s > 0; s >>= 1) {
        if (t < s) red[t] = fmaxf(red[t], red[t + s]);
        __syncthreads();
    }
    float nrm = red[0];
    float scale = 1.0f / (nrm * nrm + 1e-6f);
    float* inv = g_invA + (size_t)bh * Ll * Ll;
    for (int idx = t; idx < Ll * Ll; idx += 256) {
        int i = idx / Ll, j = idx % Ll;
        inv[idx] = M2b[(size_t)j * Ll + i] * scale;
    }
}

__global__ void ycls_kernel()
{
    int bh = blockIdx.x;
    int t  = threadIdx.x;        // 256 threads
    __shared__ float sc[Ll];
    __shared__ float qc[Dd];
    if (t < Dd) qc[t] = g_q[(size_t)bh * NT * Dd + t];
    __syncthreads();
    const float* kl = g_kland + ((size_t)bh * Ll + t) * Dd;
    float dot = 0.f;
#pragma unroll
    for (int d = 0; d < Dd; d++) dot += qc[d] * kl[d];
    float dist = g_qcn[bh] + g_kln[(size_t)bh * Ll + t] - 2.0f * dot;
    sc[t] = expf(dist * NEG_INV_TAU);
    __syncthreads();
    if (t < Dd) {
        float s = 0.f;
        for (int l = 0; l < Ll; l++)
            s += sc[l] * g_Vmix[((size_t)bh * Ll + l) * Dd + t];
        int b = bh / Hh, h = bh % Hh;
        g_attn[(size_t)b * NT * Cd + h * Dd + t] = s;
    }
}

// ---------------------------------------------------------------------------
// Host launcher
// ---------------------------------------------------------------------------
template<int BM, int BN, bool BT, class Epi>
static void launch_gemm(dim3 grid, const float* A, const float* Bp,
                        int M, int Nn, int K, int lda, int ldb,
                        size_t sA, size_t sB, Epi epi)
{
    using C = GemmCfg<BM, BN, BT>;
    static bool attr_done = false;
    if (!attr_done) {
        cudaFuncSetAttribute((const void*)gemm_tc<BM, BN, BT, Epi>,
                             cudaFuncAttributeMaxDynamicSharedMemorySize,
                             C::SMEM_BYTES);
        attr_done = true;
    }
    gemm_tc<BM, BN, BT, Epi><<<grid, C::THREADS, C::SMEM_BYTES>>>(
        A, Bp, M, Nn, K, lda, ldb, sA, sB, epi);
}

extern "C" void kernel_launch(void* const* d_in, const int* in_sizes, int n_in,
                              void* d_out, int out_size)
{
    (void)in_sizes; (void)n_in; (void)out_size;
    const float* x      = (const float*)d_in[0];
    const float* qkv_w  = (const float*)d_in[1];
    const float* qkv_b  = (const float*)d_in[2];
    const float* proj_w = (const float*)d_in[3];
    const float* proj_b = (const float*)d_in[4];
    float* out = (float*)d_out;

    float *p_q, *p_k, *p_v, *p_qland, *p_kland;
    float *p_qpn, *p_kpn, *p_qln, *p_kln;
    float *p_M1, *p_M2, *p_M3, *p_invA, *p_invB, *p_T, *p_KV, *p_Vmix, *p_attn;
    cudaGetSymbolAddress((void**)&p_q, g_q);
    cudaGetSymbolAddress((void**)&p_k, g_k);
    cudaGetSymbolAddress((void**)&p_v, g_v);
    cudaGetSymbolAddress((void**)&p_qland, g_qland);
    cudaGetSymbolAddress((void**)&p_kland, g_kland);
    cudaGetSymbolAddress((void**)&p_qpn, g_qpn);
    cudaGetSymbolAddress((void**)&p_kpn, g_kpn);
    cudaGetSymbolAddress((void**)&p_qln, g_qln);
    cudaGetSymbolAddress((void**)&p_kln, g_kln);
    cudaGetSymbolAddress((void**)&p_M1, g_M1);
    cudaGetSymbolAddress((void**)&p_M2, g_M2);
    cudaGetSymbolAddress((void**)&p_M3, g_M3);
    cudaGetSymbolAddress((void**)&p_invA, g_invA);
    cudaGetSymbolAddress((void**)&p_invB, g_invB);
    cudaGetSymbolAddress((void**)&p_T, g_T);
    cudaGetSymbolAddress((void**)&p_KV, g_KV);
    cudaGetSymbolAddress((void**)&p_Vmix, g_Vmix);
    cudaGetSymbolAddress((void**)&p_attn, g_attn);

    const int M_tok = Bn * NT;   // 16400
    const int gy_tok = (M_tok + 127) / 128;

    // 1. QKV projection: x @ qkv_w^T + b, scattered into q/k/v [B][H][N][D]
    launch_gemm<128, 128, true>(dim3(3 * Cd / 128, gy_tok, 1),
        x, qkv_w, M_tok, 3 * Cd, Cd, Cd, Cd, 0, 0, EpiQKV{qkv_b});

    // 2. pooling + norms
    pool_kernel<<<(BH * Ll * Dd + 255) / 256, 256>>>();
    norms_patch_kernel<<<(BH * NP + 255) / 256, 256>>>();
    norms_land_kernel<<<(BH * Ll + 255) / 256, 256>>>();

    // 3. Gauss kernel matrices
    launch_gemm<128, 128, true>(dim3(Ll / 128, Ll / 128, BH),       // M2
        p_qland, p_kland, Ll, Ll, Dd, Dd, Dd,
        (size_t)Ll * Dd, (size_t)Ll * Dd,
        EpiGauss{p_qln, p_kln, p_M2, Ll, Ll, Ll, (size_t)Ll * Ll});
    launch_gemm<128, 128, true>(dim3(Ll / 128, NP / 128, BH),       // M1
        p_q + Dd, p_kland, NP, Ll, Dd, Dd, Dd,
        (size_t)NT * Dd, (size_t)Ll * Dd,
        EpiGauss{p_qpn, p_kln, p_M1, NP, Ll, Ll, (size_t)NP * Ll});
    launch_gemm<128, 128, true>(dim3(NP / 128, Ll / 128, BH),       // M3
        p_qland, p_k + Dd, Ll, NP, Dd, Dd, Dd,
        (size_t)Ll * Dd, (size_t)NT * Dd,
        EpiGauss{p_qln, p_kpn, p_M3, Ll, NP, NP, (size_t)Ll * NP});

    // 4. Newton iterations for M2^-1
    newton_init_kernel<<<BH, 256>>>();
    {
        float* cur = p_invA;
        float* nxt = p_invB;
        dim3 grid(Ll / 128, Ll / 128, BH);
        for (int it = 0; it < NEWTON_ITERS; it++) {
            launch_gemm<128, 128, false>(grid,
                p_M2, cur, Ll, Ll, Ll, Ll, Ll,
                (size_t)Ll * Ll, (size_t)Ll * Ll,
                EpiPlain{p_T, Ll, (size_t)Ll * Ll});
            launch_gemm<128, 128, false>(grid,
                cur, p_T, Ll, Ll, Ll, Ll, Ll,
                (size_t)Ll * Ll, (size_t)Ll * Ll,
                EpiNewton{cur, nxt});
            float* tmp = cur; cur = nxt; nxt = tmp;
        }
        // NEWTON_ITERS even -> result in p_invA
    }

    // 5. KV = M3 @ v_patch : [L x D]
    launch_gemm<128, 64, false>(dim3(1, Ll / 128, BH),
        p_M3, p_v + Dd, Ll, Dd, NP, NP, Dd,
        (size_t)Ll * NP, (size_t)NT * Dd,
        EpiPlain{p_KV, Dd, (size_t)Ll * Dd});
    // 6. V_mixed = M2_inv @ KV : [L x D]
    launch_gemm<128, 64, false>(dim3(1, Ll / 128, BH),
        p_invA, p_KV, Ll, Dd, Ll, Ll, Dd,
        (size_t)Ll * Ll, (size_t)Ll * Dd,
        EpiPlain{p_Vmix, Dd, (size_t)Ll * Dd});
    // 7. y_patch = M1 @ V_mixed -> attn[b][1..1024][h*64+d]
    launch_gemm<128, 64, false>(dim3(1, NP / 128, BH),
        p_M1, p_Vmix, NP, Dd, Ll, Ll, Dd,
        (size_t)NP * Ll, (size_t)Ll * Dd, EpiYPatch{});
    // 8. y_cls -> attn[b][0][h*64+d]
    ycls_kernel<<<BH, 256>>>();

    // 9. output projection: attn @ proj_w^T + proj_b
    launch_gemm<128, 128, true>(dim3(Cd / 128, gy_tok, 1),
        p_attn, proj_w, M_tok, Cd, Cd, Cd, Cd, 0, 0, EpiProj{proj_b, out});
}

// round 6
// speedup vs baseline: 1.1986x; 1.0599x over previous
#include <cuda_runtime.h>
#include <math.h>
#include <stddef.h>

// ---------------------------------------------------------------------------
// Problem constants
// ---------------------------------------------------------------------------
#define Bn   16
#define NT   1025            // tokens (1 cls + 1024 patches)
#define Cd   768
#define Hh   12
#define Dd   64
#define NP   1024            // patch tokens
#define Ll   256             // landmarks (16x16)
#define BH   (Bn*Hh)         // 192
#define NEWTON_ITERS 6
#define NEG_INV_TAU (-0.125f)   // tau = sqrt(64) = 8

// ---------------------------------------------------------------------------
// Scratch (static device globals)
// ---------------------------------------------------------------------------
__device__ float g_q[BH * NT * Dd];
__device__ float g_k[BH * NT * Dd];
__device__ float g_v[BH * NT * Dd];
__device__ float g_qland[BH * Ll * Dd];
__device__ float g_kland[BH * Ll * Dd];
__device__ float g_qpn[BH * NP];
__device__ float g_kpn[BH * NP];
__device__ float g_qln[BH * Ll];
__device__ float g_kln[BH * Ll];
__device__ float g_qcn[BH];
__device__ float g_M1[(size_t)BH * NP * Ll];
__device__ float g_M2[(size_t)BH * Ll * Ll];
__device__ float g_M3[(size_t)BH * Ll * NP];
__device__ float g_invA[(size_t)BH * Ll * Ll];
__device__ float g_invB[(size_t)BH * Ll * Ll];
__device__ float g_T[(size_t)BH * Ll * Ll];
__device__ float g_KV[BH * Ll * Dd];
__device__ float g_Vmix[BH * Ll * Dd];
__device__ float g_attn[(size_t)Bn * NT * Cd];

// ---------------------------------------------------------------------------
// Epilogue functors
// ---------------------------------------------------------------------------
struct EpiQKV {
    const float* bias;
    __device__ __forceinline__ void store(int, int m, int j, float acc) const {
        int b = m / NT, n = m % NT;
        int part = j / Cd;
        int rem  = j % Cd;
        int h = rem / Dd, d = rem % Dd;
        float* dst = (part == 0) ? g_q : ((part == 1) ? g_k : g_v);
        dst[(((size_t)b * Hh + h) * NT + n) * Dd + d] = acc + bias[j];
    }
};

struct EpiGauss {
    const float* xn; const float* yn; float* out;
    int sxn; int syn; int ldc; size_t sout;
    __device__ __forceinline__ void store(int bh, int m, int n, float acc) const {
        float dist = xn[(size_t)bh * sxn + m] + yn[(size_t)bh * syn + n] - 2.0f * acc;
        out[(size_t)bh * sout + (size_t)m * ldc + n] = expf(dist * NEG_INV_TAU);
    }
};

struct EpiPlain {
    float* out; int ldc; size_t s;
    __device__ __forceinline__ void store(int bh, int m, int n, float acc) const {
        out[(size_t)bh * s + (size_t)m * ldc + n] = acc;
    }
};

struct EpiNewton {   // out = 2*inv - acc
    const float* inv; float* out;
    __device__ __forceinline__ void store(int bh, int m, int n, float acc) const {
        size_t off = ((size_t)bh * Ll + m) * Ll + n;
        out[off] = 2.0f * inv[off] - acc;
    }
};

struct EpiYPatch {
    __device__ __forceinline__ void store(int bh, int m, int j, float acc) const {
        int b = bh / Hh, h = bh % Hh;
        g_attn[((size_t)b * NT + (m + 1)) * Cd + h * Dd + j] = acc;
    }
};

struct EpiProj {
    const float* bias; float* out;
    __device__ __forceinline__ void store(int, int m, int j, float acc) const {
        out[(size_t)m * Cd + j] = acc + bias[j];
    }
};

// ---------------------------------------------------------------------------
// TF32 helpers
// ---------------------------------------------------------------------------
__device__ __forceinline__ unsigned f2t(float f) {
    unsigned u;
    asm("cvt.rna.tf32.f32 %0, %1;" : "=r"(u) : "f"(f));
    return u;
}

__device__ __forceinline__ void mma_tf32(float* c, const unsigned* a, const unsigned* b) {
    asm volatile(
        "mma.sync.aligned.m16n8k8.row.col.f32.tf32.tf32.f32 "
        "{%0,%1,%2,%3}, {%4,%5,%6,%7}, {%8,%9}, {%0,%1,%2,%3};"
        : "+f"(c[0]), "+f"(c[1]), "+f"(c[2]), "+f"(c[3])
        : "r"(a[0]), "r"(a[1]), "r"(a[2]), "r"(a[3]), "r"(b[0]), "r"(b[1]));
}

// ---------------------------------------------------------------------------
// Fragment-ordered synchronous TF32 GEMM.  C = A(MxK,row-major,lda) @ op(B)
//   BT=true : B is [N x K] row-major (C = A @ B^T)
//   BT=false: B is [K x N] row-major (C = A @ B)
// smem holds tf32 in MMA-fragment order:
//   As[mblk(16 rows)][kblk(8 cols)][lane][4]  -> one LDS.128 per A fragment
//   Bs[nblk(8 cols)][kblk(8 rows)][lane][2]   -> one LDS.64  per B fragment
// Requires: K % 32 == 0, Nn % BN == 0, lda/ldb % 4 == 0. M may be ragged.
// ---------------------------------------------------------------------------
template<int BM, int BN, bool BT>
struct GemmCfg {
    static constexpr int BK = 32;
    static constexpr int WARPS_M = BM / 64;
    static constexpr int WARPS_N = BN / 32;
    static constexpr int THREADS = WARPS_M * WARPS_N * 32;
    static constexpr int APITCH = 132;   // 128 + 4 pad (u32)
    static constexpr int BPITCH = 68;    // 64 + 4 pad (u32)
    static constexpr int ASZ = (BM / 16) * 4 * APITCH;
    static constexpr int BSZ = (BN / 8) * 4 * BPITCH;
    static constexpr int AQ  = (BM * 8) / THREADS;   // float4 loads per thread
    static constexpr int BQ  = (BN * 8) / THREADS;
};

template<int BM, int BN, bool BT, class Epi>
__global__ void __launch_bounds__(GemmCfg<BM,BN,BT>::THREADS)
gemm_tc(const float* __restrict__ A, const float* __restrict__ Bp,
        int M, int Nn, int K, int lda, int ldb,
        size_t sA, size_t sB, Epi epi)
{
    using C = GemmCfg<BM, BN, BT>;
    constexpr int THREADS = C::THREADS;

    __shared__ __align__(16) unsigned As[C::ASZ];
    __shared__ __align__(16) unsigned Bs[C::BSZ];

    const int bh = blockIdx.z;
    A  += (size_t)bh * sA;
    Bp += (size_t)bh * sB;
    const int m0 = blockIdx.y * BM;
    const int n0 = blockIdx.x * BN;
    const int tid  = threadIdx.x;
    const int lane = tid & 31;
    const int warp = tid >> 5;
    const int wm = warp / C::WARPS_N;
    const int wn = warp % C::WARPS_N;
    const int gid = lane >> 2;      // 0..7
    const int tig = lane & 3;       // 0..3

    float acc[4][4][4];
#pragma unroll
    for (int i = 0; i < 4; i++)
#pragma unroll
        for (int j = 0; j < 4; j++)
#pragma unroll
            for (int r = 0; r < 4; r++) acc[i][j][r] = 0.0f;

    for (int k0 = 0; k0 < K; k0 += C::BK) {
        // ---- A tile -> fragment layout ----
#pragma unroll
        for (int t = 0; t < C::AQ; t++) {
            int i  = tid + t * THREADS;
            int m  = i >> 3;            // row in tile
            int kq = i & 7;             // which float4 along k
            bool v = (m0 + m < M);
            float4 val = *(const float4*)&A[(size_t)(v ? (m0 + m) : m0) * lda + k0 + kq * 4];
            if (!v) val = make_float4(0.f, 0.f, 0.f, 0.f);
            int mb   = m >> 4;
            int r    = m & 15;
            int gidA = r & 7;
            int hi   = r >> 3;          // 0/1
            int kb   = kq >> 1;
            int kh   = kq & 1;          // 0/1 (k half within 8)
            // addr = (mb*4+kb)*APITCH + lane*4 + slot;  lane=gidA*4+e, slot=hi+2*kh
            unsigned* dst = &As[(mb * 4 + kb) * C::APITCH + gidA * 16 + hi + 2 * kh];
            dst[0]  = f2t(val.x);
            dst[4]  = f2t(val.y);
            dst[8]  = f2t(val.z);
            dst[12] = f2t(val.w);
        }
        // ---- B tile -> fragment layout ----
        if (BT) {   // B [N x K] row-major
#pragma unroll
            for (int t = 0; t < C::BQ; t++) {
                int i  = tid + t * THREADS;
                int n  = i >> 3;
                int kq = i & 7;
                float4 val = *(const float4*)&Bp[(size_t)(n0 + n) * ldb + k0 + kq * 4];
                int nb   = n >> 3;
                int gidB = n & 7;
                int kb   = kq >> 1;
                int kh   = kq & 1;
                // addr = (nb*4+kb)*BPITCH + lane*2 + slot; lane=gidB*4+e, slot=kh
                unsigned* dst = &Bs[(nb * 4 + kb) * C::BPITCH + gidB * 8 + kh];
                dst[0] = f2t(val.x);
                dst[2] = f2t(val.y);
                dst[4] = f2t(val.z);
                dst[6] = f2t(val.w);
            }
        } else {    // B [K x N] row-major
#pragma unroll
            for (int t = 0; t < C::BQ; t++) {
                int i  = tid + t * THREADS;
                int kr = i / (BN / 4);       // k row in tile (0..31)
                int nq = i % (BN / 4);       // which float4 along n
                float4 val = *(const float4*)&Bp[(size_t)(k0 + kr) * ldb + n0 + nq * 4];
                int kb  = kr >> 3;
                int kkr = kr & 7;
                int tg  = kkr & 3;
                int kh  = kkr >> 2;          // slot
                int nb  = nq >> 1;
                int g0  = (nq & 1) * 4;
                // lane = (g0+e)*4 + tg ; addr = (nb*4+kb)*BPITCH + lane*2 + kh
                unsigned* dst = &Bs[(nb * 4 + kb) * C::BPITCH + (g0 * 4 + tg) * 2 + kh];
                dst[0]  = f2t(val.x);
                dst[8]  = f2t(val.y);
                dst[16] = f2t(val.z);
                dst[24] = f2t(val.w);
            }
        }
        __syncthreads();

        // ---- compute: vectorized fragment loads ----
#pragma unroll
        for (int kb = 0; kb < 4; kb++) {
            uint4 af[4];
            uint2 bf[4];
#pragma unroll
            for (int i = 0; i < 4; i++)
                af[i] = *(const uint4*)&As[((wm * 4 + i) * 4 + kb) * C::APITCH + lane * 4];
#pragma unroll
            for (int j = 0; j < 4; j++)
                bf[j] = *(const uint2*)&Bs[((wn * 4 + j) * 4 + kb) * C::BPITCH + lane * 2];
#pragma unroll
            for (int i = 0; i < 4; i++)
#pragma unroll
                for (int j = 0; j < 4; j++)
                    mma_tf32(acc[i][j], (const unsigned*)&af[i], (const unsigned*)&bf[j]);
        }
        __syncthreads();
    }

    // ---- epilogue (N exact multiple of BN; only M ragged) ----
#pragma unroll
    for (int i = 0; i < 4; i++) {
        int rm = m0 + wm * 64 + i * 16 + gid;
#pragma unroll
        for (int j = 0; j < 4; j++) {
            int cn = n0 + wn * 32 + j * 8 + tig * 2;
            if (rm < M) {
                epi.store(bh, rm, cn,     acc[i][j][0]);
                epi.store(bh, rm, cn + 1, acc[i][j][1]);
            }
            if (rm + 8 < M) {
                epi.store(bh, rm + 8, cn,     acc[i][j][2]);
                epi.store(bh, rm + 8, cn + 1, acc[i][j][3]);
            }
        }
    }
}

// ---------------------------------------------------------------------------
// Small helper kernels
// ---------------------------------------------------------------------------
__global__ void pool_kernel()
{
    int idx = blockIdx.x * blockDim.x + threadIdx.x;
    if (idx >= BH * Ll * Dd) return;
    int d  = idx % Dd;
    int l  = (idx / Dd) % Ll;
    int bh = idx / (Dd * Ll);
    int lr = l / 16, lc = l % 16;
    float sq = 0.f, sk = 0.f;
#pragma unroll
    for (int r = 0; r < 2; r++)
#pragma unroll
        for (int c = 0; c < 2; c++) {
            int p = (2 * lr + r) * 32 + (2 * lc + c);
            size_t off = ((size_t)bh * NT + (p + 1)) * Dd + d;
            sq += g_q[off];
            sk += g_k[off];
        }
    g_qland[((size_t)bh * Ll + l) * Dd + d] = sq * 0.25f;
    g_kland[((size_t)bh * Ll + l) * Dd + d] = sk * 0.25f;
}

__device__ __forceinline__ float row_sq_norm(const float* p)
{
    const float4* p4 = (const float4*)p;
    float s = 0.f;
#pragma unroll
    for (int i = 0; i < Dd / 4; i++) {
        float4 v = p4[i];
        s += v.x * v.x + v.y * v.y + v.z * v.z + v.w * v.w;
    }
    return s;
}

__global__ void norms_patch_kernel()
{
    int idx = blockIdx.x * blockDim.x + threadIdx.x;
    if (idx >= BH * NP) return;
    int bh = idx / NP, p = idx % NP;
    size_t off = ((size_t)bh * NT + (p + 1)) * Dd;
    g_qpn[idx] = row_sq_norm(&g_q[off]);
    g_kpn[idx] = row_sq_norm(&g_k[off]);
}

__global__ void norms_land_kernel()
{
    int idx = blockIdx.x * blockDim.x + threadIdx.x;
    if (idx >= BH * Ll) return;
    g_qln[idx] = row_sq_norm(&g_qland[(size_t)idx * Dd]);
    g_kln[idx] = row_sq_norm(&g_kland[(size_t)idx * Dd]);
    if (idx < BH)
        g_qcn[idx] = row_sq_norm(&g_q[(size_t)idx * NT * Dd]);  // n = 0 (cls)
}

__global__ void newton_init_kernel()
{
    int bh = blockIdx.x;
    int t  = threadIdx.x;        // 256 threads, one row each
    const float* M2b = g_M2 + (size_t)bh * Ll * Ll;
    const float* row = M2b + (size_t)t * Ll;
    float rs = 0.f;
    for (int j = 0; j < Ll; j++) rs += fabsf(row[j]);
    __shared__ float red[256];
    red[t] = rs;
    __syncthreads();
    for (int s = 128; s > 0; s >>= 1) {
        if (t < s) red[t] = fmaxf(red[t], red[t + s]);
        __syncthreads();
    }
    float nrm = red[0];
    float scale = 1.0f / (nrm * nrm + 1e-6f);
    float* inv = g_invA + (size_t)bh * Ll * Ll;
    for (int idx = t; idx < Ll * Ll; idx += 256) {
        int i = idx / Ll, j = idx % Ll;
        inv[idx] = M2b[(size_t)j * Ll + i] * scale;
    }
}

__global__ void ycls_kernel()
{
    int bh = blockIdx.x;
    int t  = threadIdx.x;        // 256 threads
    __shared__ float sc[Ll];
    __shared__ float qc[Dd];
    if (t < Dd) qc[t] = g_q[(size_t)bh * NT * Dd + t];
    __syncthreads();
    const float* kl = g_kland + ((size_t)bh * Ll + t) * Dd;
    float dot = 0.f;
#pragma unroll
    for (int d = 0; d < Dd; d++) dot += qc[d] * kl[d];
    float dist = g_qcn[bh] + g_kln[(size_t)bh * Ll + t] - 2.0f * dot;
    sc[t] = expf(dist * NEG_INV_TAU);
    __syncthreads();
    if (t < Dd) {
        float s = 0.f;
        for (int l = 0; l < Ll; l++)
            s += sc[l] * g_Vmix[((size_t)bh * Ll + l) * Dd + t];
        int b = bh / Hh, h = bh % Hh;
        g_attn[(size_t)b * NT * Cd + h * Dd + t] = s;
    }
}

// ---------------------------------------------------------------------------
// Host launcher
// ---------------------------------------------------------------------------
template<int BM, int BN, bool BT, class Epi>
static void launch_gemm(dim3 grid, const float* A, const float* Bp,
                        int M, int Nn, int K, int lda, int ldb,
                        size_t sA, size_t sB, Epi epi)
{
    using C = GemmCfg<BM, BN, BT>;
    gemm_tc<BM, BN, BT, Epi><<<grid, C::THREADS>>>(
        A, Bp, M, Nn, K, lda, ldb, sA, sB, epi);
}

extern "C" void kernel_launch(void* const* d_in, const int* in_sizes, int n_in,
                              void* d_out, int out_size)
{
    (void)in_sizes; (void)n_in; (void)out_size;
    const float* x      = (const float*)d_in[0];
    const float* qkv_w  = (const float*)d_in[1];
    const float* qkv_b  = (const float*)d_in[2];
    const float* proj_w = (const float*)d_in[3];
    const float* proj_b = (const float*)d_in[4];
    float* out = (float*)d_out;

    float *p_q, *p_k, *p_v, *p_qland, *p_kland;
    float *p_qpn, *p_kpn, *p_qln, *p_kln;
    float *p_M1, *p_M2, *p_M3, *p_invA, *p_invB, *p_T, *p_KV, *p_Vmix, *p_attn;
    cudaGetSymbolAddress((void**)&p_q, g_q);
    cudaGetSymbolAddress((void**)&p_k, g_k);
    cudaGetSymbolAddress((void**)&p_v, g_v);
    cudaGetSymbolAddress((void**)&p_qland, g_qland);
    cudaGetSymbolAddress((void**)&p_kland, g_kland);
    cudaGetSymbolAddress((void**)&p_qpn, g_qpn);
    cudaGetSymbolAddress((void**)&p_kpn, g_kpn);
    cudaGetSymbolAddress((void**)&p_qln, g_qln);
    cudaGetSymbolAddress((void**)&p_kln, g_kln);
    cudaGetSymbolAddress((void**)&p_M1, g_M1);
    cudaGetSymbolAddress((void**)&p_M2, g_M2);
    cudaGetSymbolAddress((void**)&p_M3, g_M3);
    cudaGetSymbolAddress((void**)&p_invA, g_invA);
    cudaGetSymbolAddress((void**)&p_invB, g_invB);
    cudaGetSymbolAddress((void**)&p_T, g_T);
    cudaGetSymbolAddress((void**)&p_KV, g_KV);
    cudaGetSymbolAddress((void**)&p_Vmix, g_Vmix);
    cudaGetSymbolAddress((void**)&p_attn, g_attn);

    const int M_tok = Bn * NT;   // 16400
    const int gy_tok = (M_tok + 127) / 128;

    // 1. QKV projection: x @ qkv_w^T + b, scattered into q/k/v [B][H][N][D]
    launch_gemm<128, 128, true>(dim3(3 * Cd / 128, gy_tok, 1),
        x, qkv_w, M_tok, 3 * Cd, Cd, Cd, Cd, 0, 0, EpiQKV{qkv_b});

    // 2. pooling + norms
    pool_kernel<<<(BH * Ll * Dd + 255) / 256, 256>>>();
    norms_patch_kernel<<<(BH * NP + 255) / 256, 256>>>();
    norms_land_kernel<<<(BH * Ll + 255) / 256, 256>>>();

    // 3. Gauss kernel matrices
    launch_gemm<128, 128, true>(dim3(Ll / 128, Ll / 128, BH),       // M2
        p_qland, p_kland, Ll, Ll, Dd, Dd, Dd,
        (size_t)Ll * Dd, (size_t)Ll * Dd,
        EpiGauss{p_qln, p_kln, p_M2, Ll, Ll, Ll, (size_t)Ll * Ll});
    launch_gemm<128, 128, true>(dim3(Ll / 128, NP / 128, BH),       // M1
        p_q + Dd, p_kland, NP, Ll, Dd, Dd, Dd,
        (size_t)NT * Dd, (size_t)Ll * Dd,
        EpiGauss{p_qpn, p_kln, p_M1, NP, Ll, Ll, (size_t)NP * Ll});
    launch_gemm<128, 128, true>(dim3(NP / 128, Ll / 128, BH),       // M3
        p_qland, p_k + Dd, Ll, NP, Dd, Dd, Dd,
        (size_t)Ll * Dd, (size_t)NT * Dd,
        EpiGauss{p_qln, p_kpn, p_M3, Ll, NP, NP, (size_t)Ll * NP});

    // 4. Newton iterations for M2^-1
    newton_init_kernel<<<BH, 256>>>();
    {
        float* cur = p_invA;
        float* nxt = p_invB;
        dim3 grid(Ll / 128, Ll / 128, BH);
        for (int it = 0; it < NEWTON_ITERS; it++) {
            launch_gemm<128, 128, false>(grid,
                p_M2, cur, Ll, Ll, Ll, Ll, Ll,
                (size_t)Ll * Ll, (size_t)Ll * Ll,
                EpiPlain{p_T, Ll, (size_t)Ll * Ll});
            launch_gemm<128, 128, false>(grid,
                cur, p_T, Ll, Ll, Ll, Ll, Ll,
                (size_t)Ll * Ll, (size_t)Ll * Ll,
                EpiNewton{cur, nxt});
            float* tmp = cur; cur = nxt; nxt = tmp;
        }
        // NEWTON_ITERS even -> result in p_invA
    }

    // 5. KV = M3 @ v_patch : [L x D]
    launch_gemm<128, 64, false>(dim3(1, Ll / 128, BH),
        p_M3, p_v + Dd, Ll, Dd, NP, NP, Dd,
        (size_t)Ll * NP, (size_t)NT * Dd,
        EpiPlain{p_KV, Dd, (size_t)Ll * Dd});
    // 6. V_mixed = M2_inv @ KV : [L x D]
    launch_gemm<128, 64, false>(dim3(1, Ll / 128, BH),
        p_invA, p_KV, Ll, Dd, Ll, Ll, Dd,
        (size_t)Ll * Ll, (size_t)Ll * Dd,
        EpiPlain{p_Vmix, Dd, (size_t)Ll * Dd});
    // 7. y_patch = M1 @ V_mixed -> attn[b][1..1024][h*64+d]
    launch_gemm<128, 64, false>(dim3(1, NP / 128, BH),
        p_M1, p_Vmix, NP, Dd, Ll, Ll, Dd,
        (size_t)NP * Ll, (size_t)Ll * Dd, EpiYPatch{});
    // 8. y_cls -> attn[b][0][h*64+d]
    ycls_kernel<<<BH, 256>>>();

    // 9. output projection: attn @ proj_w^T + proj_b
    launch_gemm<128, 128, true>(dim3(Cd / 128, gy_tok, 1),
        p_attn, proj_w, M_tok, Cd, Cd, Cd, Cd, 0, 0, EpiProj{proj_b, out});
}

// round 8
// speedup vs baseline: 1.4834x; 1.2377x over previous
#include <cuda_runtime.h>
#include <math.h>
#include <stddef.h>

// ---------------------------------------------------------------------------
// Problem constants
// ---------------------------------------------------------------------------
#define Bn   16
#define NT   1025            // tokens (1 cls + 1024 patches)
#define Cd   768
#define Hh   12
#define Dd   64
#define NP   1024            // patch tokens
#define Ll   256             // landmarks (16x16)
#define BH   (Bn*Hh)         // 192
#define NEWTON_ITERS 6
#define NEG_INV_TAU (-0.125f)   // tau = sqrt(64) = 8

// ---------------------------------------------------------------------------
// Scratch (static device globals)
// ---------------------------------------------------------------------------
__device__ float g_q[BH * NT * Dd];
__device__ float g_k[BH * NT * Dd];
__device__ float g_v[BH * NT * Dd];
__device__ float g_qland[BH * Ll * Dd];
__device__ float g_kland[BH * Ll * Dd];
__device__ float g_qpn[BH * NP];
__device__ float g_kpn[BH * NP];
__device__ float g_qln[BH * Ll];
__device__ float g_kln[BH * Ll];
__device__ float g_qcn[BH];
__device__ float g_M1[(size_t)BH * NP * Ll];
__device__ float g_M2[(size_t)BH * Ll * Ll];
__device__ float g_M3[(size_t)BH * Ll * NP];
__device__ float g_invA[(size_t)BH * Ll * Ll];
__device__ float g_invB[(size_t)BH * Ll * Ll];
__device__ float g_T[(size_t)BH * Ll * Ll];
__device__ float g_KV[BH * Ll * Dd];
__device__ float g_Vmix[BH * Ll * Dd];
__device__ float g_attn[(size_t)Bn * NT * Cd];

// ---------------------------------------------------------------------------
// Epilogue functors
// ---------------------------------------------------------------------------
struct EpiQKV {
    const float* bias;
    __device__ __forceinline__ void store(int, int m, int j, float acc) const {
        int b = m / NT, n = m % NT;
        int part = j / Cd;
        int rem  = j % Cd;
        int h = rem / Dd, d = rem % Dd;
        float* dst = (part == 0) ? g_q : ((part == 1) ? g_k : g_v);
        dst[(((size_t)b * Hh + h) * NT + n) * Dd + d] = acc + bias[j];
    }
};

struct EpiGauss {
    const float* xn; const float* yn; float* out;
    int sxn; int syn; int ldc; size_t sout;
    __device__ __forceinline__ void store(int bh, int m, int n, float acc) const {
        float dist = xn[(size_t)bh * sxn + m] + yn[(size_t)bh * syn + n] - 2.0f * acc;
        out[(size_t)bh * sout + (size_t)m * ldc + n] = expf(dist * NEG_INV_TAU);
    }
};

struct EpiPlain {
    float* out; int ldc; size_t s;
    __device__ __forceinline__ void store(int bh, int m, int n, float acc) const {
        out[(size_t)bh * s + (size_t)m * ldc + n] = acc;
    }
};

struct EpiNewton {   // out = 2*inv - acc
    const float* inv; float* out;
    __device__ __forceinline__ void store(int bh, int m, int n, float acc) const {
        size_t off = ((size_t)bh * Ll + m) * Ll + n;
        out[off] = 2.0f * inv[off] - acc;
    }
};

struct EpiYPatch {
    __device__ __forceinline__ void store(int bh, int m, int j, float acc) const {
        int b = bh / Hh, h = bh % Hh;
        g_attn[((size_t)b * NT + (m + 1)) * Cd + h * Dd + j] = acc;
    }
};

struct EpiProj {
    const float* bias; float* out;
    __device__ __forceinline__ void store(int, int m, int j, float acc) const {
        out[(size_t)m * Cd + j] = acc + bias[j];
    }
};

// ---------------------------------------------------------------------------
// TF32 / LDSM helpers
// ---------------------------------------------------------------------------
__device__ __forceinline__ unsigned f2t(float f) {
    unsigned u;
    asm("cvt.rna.tf32.f32 %0, %1;" : "=r"(u) : "f"(f));
    return u;
}

__device__ __forceinline__ void mma_tf32(float* c, const unsigned* a, const unsigned* b) {
    asm volatile(
        "mma.sync.aligned.m16n8k8.row.col.f32.tf32.tf32.f32 "
        "{%0,%1,%2,%3}, {%4,%5,%6,%7}, {%8,%9}, {%0,%1,%2,%3};"
        : "+f"(c[0]), "+f"(c[1]), "+f"(c[2]), "+f"(c[3])
        : "r"(a[0]), "r"(a[1]), "r"(a[2]), "r"(a[3]), "r"(b[0]), "r"(b[1]));
}

__device__ __forceinline__ void ldsm4(unsigned* r, const unsigned* p) {
    unsigned a = (unsigned)__cvta_generic_to_shared((void*)p);
    asm volatile("ldmatrix.sync.aligned.m8n8.x4.shared.b16 {%0,%1,%2,%3}, [%4];"
                 : "=r"(r[0]), "=r"(r[1]), "=r"(r[2]), "=r"(r[3]) : "r"(a));
}

// ---------------------------------------------------------------------------
// Synchronous TF32 tensor-core GEMM (Round-2 structure + LDSM fragment loads).
//   C = A(MxK, row-major, lda) @ op(B)
//   BT=true : B is [N x K] row-major (C = A @ B^T)
//   BT=false: B is [K x N] row-major (C = A @ B)
// smem holds tf32 in [m][k] / [n][k] / [k][n] layout (cvt once at store).
// Fragments loaded with ldmatrix.x4 (A always; B in BT mode).
// Requires: K % 32 == 0, Nn % BN == 0, lda/ldb % 4 == 0. M may be ragged.
// ---------------------------------------------------------------------------
template<int BM, int BN, bool BT, class Epi>
__global__ void __launch_bounds__((BM / 64) * (BN / 32) * 32)
gemm_tc(const float* __restrict__ A, const float* __restrict__ Bp,
        int M, int Nn, int K, int lda, int ldb,
        size_t sA, size_t sB, Epi epi)
{
    constexpr int BK = 32;
    constexpr int WARPS_M = BM / 64;
    constexpr int WARPS_N = BN / 32;
    constexpr int THREADS = WARPS_M * WARPS_N * 32;
    constexpr int SA  = BK + 4;     // As / Bs(BT) row stride (u32)
    constexpr int SBN = BN + 8;     // Bs row stride, non-BT [BK][SBN]

    __shared__ __align__(16) unsigned As[BM * SA];
    __shared__ __align__(16) unsigned Bs[BT ? (BN * SA) : (BK * SBN)];

    const int bh = blockIdx.z;
    A  += (size_t)bh * sA;
    Bp += (size_t)bh * sB;
    const int m0 = blockIdx.y * BM;
    const int n0 = blockIdx.x * BN;
    const int tid  = threadIdx.x;
    const int lane = tid & 31;
    const int warp = tid >> 5;
    const int wm = warp / WARPS_N;
    const int wn = warp % WARPS_N;
    const int gid = lane >> 2;      // 0..7
    const int tig = lane & 3;       // 0..3
    const int rr  = lane & 7;       // ldmatrix row within 8-group
    const int sub = lane >> 3;      // ldmatrix sub-matrix id 0..3

    float acc[4][4][4];
#pragma unroll
    for (int i = 0; i < 4; i++)
#pragma unroll
        for (int j = 0; j < 4; j++)
#pragma unroll
            for (int r = 0; r < 4; r++) acc[i][j][r] = 0.0f;

    for (int k0 = 0; k0 < K; k0 += BK) {
        // ---- A tile -> As[m][k], tf32 (identical to Round 2) ----
#pragma unroll
        for (int t = 0; t < (BM * 8) / THREADS; t++) {
            int i  = tid + t * THREADS;
            int m  = i >> 3;
            int kq = i & 7;
            float4 v = make_float4(0.f, 0.f, 0.f, 0.f);
            if (m0 + m < M)
                v = *(const float4*)&A[(size_t)(m0 + m) * lda + k0 + kq * 4];
            uint4 u = make_uint4(f2t(v.x), f2t(v.y), f2t(v.z), f2t(v.w));
            *(uint4*)&As[m * SA + kq * 4] = u;
        }
        // ---- B tile (identical to Round 2) ----
        if (BT) {   // B [N x K] -> Bs[n][k]
#pragma unroll
            for (int t = 0; t < (BN * 8) / THREADS; t++) {
                int i  = tid + t * THREADS;
                int n  = i >> 3;
                int kq = i & 7;
                float4 v = *(const float4*)&Bp[(size_t)(n0 + n) * ldb + k0 + kq * 4];
                uint4 u = make_uint4(f2t(v.x), f2t(v.y), f2t(v.z), f2t(v.w));
                *(uint4*)&Bs[n * SA + kq * 4] = u;
            }
        } else {    // B [K x N] -> Bs[k][n]
#pragma unroll
            for (int t = 0; t < (BK * BN / 4) / THREADS; t++) {
                int i  = tid + t * THREADS;
                int kk = i / (BN / 4);
                int nq = i % (BN / 4);
                float4 v = *(const float4*)&Bp[(size_t)(k0 + kk) * ldb + n0 + nq * 4];
                uint4 u = make_uint4(f2t(v.x), f2t(v.y), f2t(v.z), f2t(v.w));
                *(uint4*)&Bs[kk * SBN + nq * 4] = u;
            }
        }
        __syncthreads();

        // ---- compute: LDSM fragment loads ----
#pragma unroll
        for (int kk = 0; kk < BK; kk += 8) {
            unsigned af[4][4], bf[4][2];
            // A fragments: one ldmatrix.x4 per 16-row block
            //  sub 0: rows r0..r0+7   @ kk    -> a0
            //  sub 1: rows r0+8..+15  @ kk    -> a1
            //  sub 2: rows r0..r0+7   @ kk+4  -> a2
            //  sub 3: rows r0+8..+15  @ kk+4  -> a3
            {
                int arow = rr + (sub & 1) * 8;
                int acol = kk + (sub >> 1) * 4;
#pragma unroll
                for (int i = 0; i < 4; i++) {
                    int row = wm * 64 + i * 16 + arow;
                    ldsm4(af[i], &As[row * SA + acol]);
                }
            }
            if (BT) {
                // B fragments: one ldmatrix.x4 per pair of 8-col n blocks
                //  sub 0: n c0..c0+7  @ kk    -> bf[j][0]
                //  sub 1: n c0..c0+7  @ kk+4  -> bf[j][1]
                //  sub 2: n c0+8..+15 @ kk    -> bf[j+1][0]
                //  sub 3: n c0+8..+15 @ kk+4  -> bf[j+1][1]
                int brow = rr + (sub >> 1) * 8;
                int bcol = kk + (sub & 1) * 4;
#pragma unroll
                for (int jp = 0; jp < 2; jp++) {
                    int n = wn * 32 + jp * 16 + brow;
                    unsigned tmp[4];
                    ldsm4(tmp, &Bs[n * SA + bcol]);
                    bf[jp * 2][0]     = tmp[0];
                    bf[jp * 2][1]     = tmp[1];
                    bf[jp * 2 + 1][0] = tmp[2];
                    bf[jp * 2 + 1][1] = tmp[3];
                }
            } else {
#pragma unroll
                for (int j = 0; j < 4; j++) {
                    int c0 = wn * 32 + j * 8 + gid;
                    bf[j][0] = Bs[(kk + tig) * SBN + c0];
                    bf[j][1] = Bs[(kk + tig + 4) * SBN + c0];
                }
            }
#pragma unroll
            for (int i = 0; i < 4; i++)
#pragma unroll
                for (int j = 0; j < 4; j++)
                    mma_tf32(acc[i][j], af[i], bf[j]);
        }
        __syncthreads();
    }

    // ---- epilogue (N exact multiple of BN; only M ragged) ----
#pragma unroll
    for (int i = 0; i < 4; i++) {
        int rm = m0 + wm * 64 + i * 16 + gid;
#pragma unroll
        for (int j = 0; j < 4; j++) {
            int cn = n0 + wn * 32 + j * 8 + tig * 2;
            if (rm < M) {
                epi.store(bh, rm, cn,     acc[i][j][0]);
                epi.store(bh, rm, cn + 1, acc[i][j][1]);
            }
            if (rm + 8 < M) {
                epi.store(bh, rm + 8, cn,     acc[i][j][2]);
                epi.store(bh, rm + 8, cn + 1, acc[i][j][3]);
            }
        }
    }
}

// ---------------------------------------------------------------------------
// Small helper kernels
// ---------------------------------------------------------------------------
__global__ void pool_kernel()
{
    int idx = blockIdx.x * blockDim.x + threadIdx.x;
    if (idx >= BH * Ll * Dd) return;
    int d  = idx % Dd;
    int l  = (idx / Dd) % Ll;
    int bh = idx / (Dd * Ll);
    int lr = l / 16, lc = l % 16;
    float sq = 0.f, sk = 0.f;
#pragma unroll
    for (int r = 0; r < 2; r++)
#pragma unroll
        for (int c = 0; c < 2; c++) {
            int p = (2 * lr + r) * 32 + (2 * lc + c);
            size_t off = ((size_t)bh * NT + (p + 1)) * Dd + d;
            sq += g_q[off];
            sk += g_k[off];
        }
    g_qland[((size_t)bh * Ll + l) * Dd + d] = sq * 0.25f;
    g_kland[((size_t)bh * Ll + l) * Dd + d] = sk * 0.25f;
}

__device__ __forceinline__ float row_sq_norm(const float* p)
{
    const float4* p4 = (const float4*)p;
    float s = 0.f;
#pragma unroll
    for (int i = 0; i < Dd / 4; i++) {
        float4 v = p4[i];
        s += v.x * v.x + v.y * v.y + v.z * v.z + v.w * v.w;
    }
    return s;
}

__global__ void norms_patch_kernel()
{
    int idx = blockIdx.x * blockDim.x + threadIdx.x;
    if (idx >= BH * NP) return;
    int bh = idx / NP, p = idx % NP;
    size_t off = ((size_t)bh * NT + (p + 1)) * Dd;
    g_qpn[idx] = row_sq_norm(&g_q[off]);
    g_kpn[idx] = row_sq_norm(&g_k[off]);
}

__global__ void norms_land_kernel()
{
    int idx = blockIdx.x * blockDim.x + threadIdx.x;
    if (idx >= BH * Ll) return;
    g_qln[idx] = row_sq_norm(&g_qland[(size_t)idx * Dd]);
    g_kln[idx] = row_sq_norm(&g_kland[(size_t)idx * Dd]);
    if (idx < BH)
        g_qcn[idx] = row_sq_norm(&g_q[(size_t)idx * NT * Dd]);  // n = 0 (cls)
}

__global__ void newton_init_kernel()
{
    int bh = blockIdx.x;
    int t  = threadIdx.x;        // 256 threads, one row each
    const float* M2b = g_M2 + (size_t)bh * Ll * Ll;
    const float* row = M2b + (size_t)t * Ll;
    float rs = 0.f;
    for (int j = 0; j < Ll; j++) rs += fabsf(row[j]);
    __shared__ float red[256];
    red[t] = rs;
    __syncthreads();
    for (int s = 128; s > 0; s >>= 1) {
        if (t < s) red[t] = fmaxf(red[t], red[t + s]);
        __syncthreads();
    }
    float nrm = red[0];
    float scale = 1.0f / (nrm * nrm + 1e-6f);
    float* inv = g_invA + (size_t)bh * Ll * Ll;
    for (int idx = t; idx < Ll * Ll; idx += 256) {
        int i = idx / Ll, j = idx % Ll;
        inv[idx] = M2b[(size_t)j * Ll + i] * scale;
    }
}

__global__ void ycls_kernel()
{
    int bh = blockIdx.x;
    int t  = threadIdx.x;        // 256 threads
    __shared__ float sc[Ll];
    __shared__ float qc[Dd];
    if (t < Dd) qc[t] = g_q[(size_t)bh * NT * Dd + t];
    __syncthreads();
    const float* kl = g_kland + ((size_t)bh * Ll + t) * Dd;
    float dot = 0.f;
#pragma unroll
    for (int d = 0; d < Dd; d++) dot += qc[d] * kl[d];
    float dist = g_qcn[bh] + g_kln[(size_t)bh * Ll + t] - 2.0f * dot;
    sc[t] = expf(dist * NEG_INV_TAU);
    __syncthreads();
    if (t < Dd) {
        float s = 0.f;
        for (int l = 0; l < Ll; l++)
            s += sc[l] * g_Vmix[((size_t)bh * Ll + l) * Dd + t];
        int b = bh / Hh, h = bh % Hh;
        g_attn[(size_t)b * NT * Cd + h * Dd + t] = s;
    }
}

// ---------------------------------------------------------------------------
// Host launcher
// ---------------------------------------------------------------------------
template<int BM, int BN, bool BT, class Epi>
static void launch_gemm(dim3 grid, const float* A, const float* Bp,
                        int M, int Nn, int K, int lda, int ldb,
                        size_t sA, size_t sB, Epi epi)
{
    constexpr int THREADS = (BM / 64) * (BN / 32) * 32;
    gemm_tc<BM, BN, BT, Epi><<<grid, THREADS>>>(
        A, Bp, M, Nn, K, lda, ldb, sA, sB, epi);
}

extern "C" void kernel_launch(void* const* d_in, const int* in_sizes, int n_in,
                              void* d_out, int out_size)
{
    (void)in_sizes; (void)n_in; (void)out_size;
    const float* x      = (const float*)d_in[0];
    const float* qkv_w  = (const float*)d_in[1];
    const float* qkv_b  = (const float*)d_in[2];
    const float* proj_w = (const float*)d_in[3];
    const float* proj_b = (const float*)d_in[4];
    float* out = (float*)d_out;

    float *p_q, *p_k, *p_v, *p_qland, *p_kland;
    float *p_qpn, *p_kpn, *p_qln, *p_kln;
    float *p_M1, *p_M2, *p_M3, *p_invA, *p_invB, *p_T, *p_KV, *p_Vmix, *p_attn;
    cudaGetSymbolAddress((void**)&p_q, g_q);
    cudaGetSymbolAddress((void**)&p_k, g_k);
    cudaGetSymbolAddress((void**)&p_v, g_v);
    cudaGetSymbolAddress((void**)&p_qland, g_qland);
    cudaGetSymbolAddress((void**)&p_kland, g_kland);
    cudaGetSymbolAddress((void**)&p_qpn, g_qpn);
    cudaGetSymbolAddress((void**)&p_kpn, g_kpn);
    cudaGetSymbolAddress((void**)&p_qln, g_qln);
    cudaGetSymbolAddress((void**)&p_kln, g_kln);
    cudaGetSymbolAddress((void**)&p_M1, g_M1);
    cudaGetSymbolAddress((void**)&p_M2, g_M2);
    cudaGetSymbolAddress((void**)&p_M3, g_M3);
    cudaGetSymbolAddress((void**)&p_invA, g_invA);
    cudaGetSymbolAddress((void**)&p_invB, g_invB);
    cudaGetSymbolAddress((void**)&p_T, g_T);
    cudaGetSymbolAddress((void**)&p_KV, g_KV);
    cudaGetSymbolAddress((void**)&p_Vmix, g_Vmix);
    cudaGetSymbolAddress((void**)&p_attn, g_attn);

    const int M_tok = Bn * NT;   // 16400
    const int gy_tok = (M_tok + 127) / 128;

    // 1. QKV projection: x @ qkv_w^T + b, scattered into q/k/v [B][H][N][D]
    launch_gemm<128, 128, true>(dim3(3 * Cd / 128, gy_tok, 1),
        x, qkv_w, M_tok, 3 * Cd, Cd, Cd, Cd, 0, 0, EpiQKV{qkv_b});

    // 2. pooling + norms
    pool_kernel<<<(BH * Ll * Dd + 255) / 256, 256>>>();
    norms_patch_kernel<<<(BH * NP + 255) / 256, 256>>>();
    norms_land_kernel<<<(BH * Ll + 255) / 256, 256>>>();

    // 3. Gauss kernel matrices
    launch_gemm<128, 128, true>(dim3(Ll / 128, Ll / 128, BH),       // M2
        p_qland, p_kland, Ll, Ll, Dd, Dd, Dd,
        (size_t)Ll * Dd, (size_t)Ll * Dd,
        EpiGauss{p_qln, p_kln, p_M2, Ll, Ll, Ll, (size_t)Ll * Ll});
    launch_gemm<128, 128, true>(dim3(Ll / 128, NP / 128, BH),       // M1
        p_q + Dd, p_kland, NP, Ll, Dd, Dd, Dd,
        (size_t)NT * Dd, (size_t)Ll * Dd,
        EpiGauss{p_qpn, p_kln, p_M1, NP, Ll, Ll, (size_t)NP * Ll});
    launch_gemm<128, 128, true>(dim3(NP / 128, Ll / 128, BH),       // M3
        p_qland, p_k + Dd, Ll, NP, Dd, Dd, Dd,
        (size_t)Ll * Dd, (size_t)NT * Dd,
        EpiGauss{p_qln, p_kpn, p_M3, Ll, NP, NP, (size_t)Ll * NP});

    // 4. Newton iterations for M2^-1
    newton_init_kernel<<<BH, 256>>>();
    {
        float* cur = p_invA;
        float* nxt = p_invB;
        dim3 grid(Ll / 128, Ll / 128, BH);
        for (int it = 0; it < NEWTON_ITERS; it++) {
            launch_gemm<128, 128, false>(grid,
                p_M2, cur, Ll, Ll, Ll, Ll, Ll,
                (size_t)Ll * Ll, (size_t)Ll * Ll,
                EpiPlain{p_T, Ll, (size_t)Ll * Ll});
            launch_gemm<128, 128, false>(grid,
                cur, p_T, Ll, Ll, Ll, Ll, Ll,
                (size_t)Ll * Ll, (size_t)Ll * Ll,
                EpiNewton{cur, nxt});
            float* tmp = cur; cur = nxt; nxt = tmp;
        }
        // NEWTON_ITERS even -> result in p_invA
    }

    // 5. KV = M3 @ v_patch : [L x D]
    launch_gemm<128, 64, false>(dim3(1, Ll / 128, BH),
        p_M3, p_v + Dd, Ll, Dd, NP, NP, Dd,
        (size_t)Ll * NP, (size_t)NT * Dd,
        EpiPlain{p_KV, Dd, (size_t)Ll * Dd});
    // 6. V_mixed = M2_inv @ KV : [L x D]
    launch_gemm<128, 64, false>(dim3(1, Ll / 128, BH),
        p_invA, p_KV, Ll, Dd, Ll, Ll, Dd,
        (size_t)Ll * Ll, (size_t)Ll * Dd,
        EpiPlain{p_Vmix, Dd, (size_t)Ll * Dd});
    // 7. y_patch = M1 @ V_mixed -> attn[b][1..1024][h*64+d]
    launch_gemm<128, 64, false>(dim3(1, NP / 128, BH),
        p_M1, p_Vmix, NP, Dd, Ll, Ll, Dd,
        (size_t)NP * Ll, (size_t)Ll * Dd, EpiYPatch{});
    // 8. y_cls -> attn[b][0][h*64+d]
    ycls_kernel<<<BH, 256>>>();

    // 9. output projection: attn @ proj_w^T + proj_b
    launch_gemm<128, 128, true>(dim3(Cd / 128, gy_tok, 1),
        p_attn, proj_w, M_tok, Cd, Cd, Cd, Cd, 0, 0, EpiProj{proj_b, out});
}

// round 9
// speedup vs baseline: 1.4994x; 1.0107x over previous
#include <cuda_runtime.h>
#include <math.h>
#include <stddef.h>

// ---------------------------------------------------------------------------
// Problem constants
// ---------------------------------------------------------------------------
#define Bn   16
#define NT   1025            // tokens (1 cls + 1024 patches)
#define Cd   768
#define Hh   12
#define Dd   64
#define NP   1024            // patch tokens
#define Ll   256             // landmarks (16x16)
#define BH   (Bn*Hh)         // 192
#define NEWTON_ITERS 6
#define NEG_INV_TAU (-0.125f)   // tau = sqrt(64) = 8

// ---------------------------------------------------------------------------
// Scratch (static device globals)
// ---------------------------------------------------------------------------
__device__ float g_q[BH * NT * Dd];
__device__ float g_k[BH * NT * Dd];
__device__ float g_v[BH * NT * Dd];
__device__ float g_qland[BH * Ll * Dd];
__device__ float g_kland[BH * Ll * Dd];
__device__ float g_qpn[BH * NP];
__device__ float g_kpn[BH * NP];
__device__ float g_qln[BH * Ll];
__device__ float g_kln[BH * Ll];
__device__ float g_qcn[BH];
__device__ float g_M1[(size_t)BH * NP * Ll];
__device__ float g_M2[(size_t)BH * Ll * Ll];
__device__ float g_M3[(size_t)BH * Ll * NP];
__device__ float g_invA[(size_t)BH * Ll * Ll];
__device__ float g_invB[(size_t)BH * Ll * Ll];
__device__ float g_T[(size_t)BH * Ll * Ll];
__device__ float g_KV[BH * Ll * Dd];
__device__ float g_Vmix[BH * Ll * Dd];
__device__ float g_attn[(size_t)Bn * NT * Cd];

// ---------------------------------------------------------------------------
// Fast exp on FMA/ALU pipes (no MUFU).
// exp(x) = 2^(x*log2e); n = round(y), f = y-n in [-0.5,0.5];
// 2^f by degree-5 Taylor in f*ln2 form (max rel err ~2.4e-6);
// scale by 2^n via integer exponent add.
// ---------------------------------------------------------------------------
__device__ __forceinline__ float fast_exp(float x)
{
    float y  = x * 1.4426950408889634f;       // log2(e)
    int   ni = __float2int_rn(y);
    float nf = (float)ni;
    float f  = y - nf;                        // [-0.5, 0.5]
    // 2^f = exp(f*ln2): Taylor coeffs ln2^k/k!
    float p = 1.3333558146e-3f;
    p = fmaf(p, f, 9.6181291076e-3f);
    p = fmaf(p, f, 5.5504108664e-2f);
    p = fmaf(p, f, 2.4022650696e-1f);
    p = fmaf(p, f, 6.9314718056e-1f);
    p = fmaf(p, f, 1.0f);
    return __int_as_float(__float_as_int(p) + (ni << 23));
}

// ---------------------------------------------------------------------------
// Epilogue functors
// ---------------------------------------------------------------------------
struct EpiQKV {
    const float* bias;
    __device__ __forceinline__ void store(int, int m, int j, float acc) const {
        int b = m / NT, n = m % NT;
        int part = j / Cd;
        int rem  = j % Cd;
        int h = rem / Dd, d = rem % Dd;
        float* dst = (part == 0) ? g_q : ((part == 1) ? g_k : g_v);
        dst[(((size_t)b * Hh + h) * NT + n) * Dd + d] = acc + bias[j];
    }
};

struct EpiGauss {
    const float* xn; const float* yn; float* out;
    int sxn; int syn; int ldc; size_t sout;
    __device__ __forceinline__ void store(int bh, int m, int n, float acc) const {
        float dist = xn[(size_t)bh * sxn + m] + yn[(size_t)bh * syn + n] - 2.0f * acc;
        out[(size_t)bh * sout + (size_t)m * ldc + n] = fast_exp(dist * NEG_INV_TAU);
    }
};

struct EpiPlain {
    float* out; int ldc; size_t s;
    __device__ __forceinline__ void store(int bh, int m, int n, float acc) const {
        out[(size_t)bh * s + (size_t)m * ldc + n] = acc;
    }
};

struct EpiNewton {   // out = 2*inv - acc
    const float* inv; float* out;
    __device__ __forceinline__ void store(int bh, int m, int n, float acc) const {
        size_t off = ((size_t)bh * Ll + m) * Ll + n;
        out[off] = 2.0f * inv[off] - acc;
    }
};

struct EpiYPatch {
    __device__ __forceinline__ void store(int bh, int m, int j, float acc) const {
        int b = bh / Hh, h = bh % Hh;
        g_attn[((size_t)b * NT + (m + 1)) * Cd + h * Dd + j] = acc;
    }
};

struct EpiProj {
    const float* bias; float* out;
    __device__ __forceinline__ void store(int, int m, int j, float acc) const {
        out[(size_t)m * Cd + j] = acc + bias[j];
    }
};

// ---------------------------------------------------------------------------
// TF32 / LDSM helpers
// ---------------------------------------------------------------------------
__device__ __forceinline__ unsigned f2t(float f) {
    unsigned u;
    asm("cvt.rna.tf32.f32 %0, %1;" : "=r"(u) : "f"(f));
    return u;
}

__device__ __forceinline__ void mma_tf32(float* c, const unsigned* a, const unsigned* b) {
    asm volatile(
        "mma.sync.aligned.m16n8k8.row.col.f32.tf32.tf32.f32 "
        "{%0,%1,%2,%3}, {%4,%5,%6,%7}, {%8,%9}, {%0,%1,%2,%3};"
        : "+f"(c[0]), "+f"(c[1]), "+f"(c[2]), "+f"(c[3])
        : "r"(a[0]), "r"(a[1]), "r"(a[2]), "r"(a[3]), "r"(b[0]), "r"(b[1]));
}

__device__ __forceinline__ void ldsm4(unsigned* r, const unsigned* p) {
    unsigned a = (unsigned)__cvta_generic_to_shared((void*)p);
    asm volatile("ldmatrix.sync.aligned.m8n8.x4.shared.b16 {%0,%1,%2,%3}, [%4];"
                 : "=r"(r[0]), "=r"(r[1]), "=r"(r[2]), "=r"(r[3]) : "r"(a));
}

// ---------------------------------------------------------------------------
// Synchronous TF32 tensor-core GEMM (Round-8 structure, unchanged).
//   C = A(MxK, row-major, lda) @ op(B)
//   BT=true : B is [N x K] row-major (C = A @ B^T)
//   BT=false: B is [K x N] row-major (C = A @ B)
// ---------------------------------------------------------------------------
template<int BM, int BN, bool BT, class Epi>
__global__ void __launch_bounds__((BM / 64) * (BN / 32) * 32)
gemm_tc(const float* __restrict__ A, const float* __restrict__ Bp,
        int M, int Nn, int K, int lda, int ldb,
        size_t sA, size_t sB, Epi epi)
{
    constexpr int BK = 32;
    constexpr int WARPS_M = BM / 64;
    constexpr int WARPS_N = BN / 32;
    constexpr int THREADS = WARPS_M * WARPS_N * 32;
    constexpr int SA  = BK + 4;     // As / Bs(BT) row stride (u32)
    constexpr int SBN = BN + 8;     // Bs row stride, non-BT [BK][SBN]

    __shared__ __align__(16) unsigned As[BM * SA];
    __shared__ __align__(16) unsigned Bs[BT ? (BN * SA) : (BK * SBN)];

    const int bh = blockIdx.z;
    A  += (size_t)bh * sA;
    Bp += (size_t)bh * sB;
    const int m0 = blockIdx.y * BM;
    const int n0 = blockIdx.x * BN;
    const int tid  = threadIdx.x;
    const int lane = tid & 31;
    const int warp = tid >> 5;
    const int wm = warp / WARPS_N;
    const int wn = warp % WARPS_N;
    const int gid = lane >> 2;      // 0..7
    const int tig = lane & 3;       // 0..3
    const int rr  = lane & 7;       // ldmatrix row within 8-group
    const int sub = lane >> 3;      // ldmatrix sub-matrix id 0..3

    float acc[4][4][4];
#pragma unroll
    for (int i = 0; i < 4; i++)
#pragma unroll
        for (int j = 0; j < 4; j++)
#pragma unroll
            for (int r = 0; r < 4; r++) acc[i][j][r] = 0.0f;

    for (int k0 = 0; k0 < K; k0 += BK) {
        // ---- A tile -> As[m][k], tf32 ----
#pragma unroll
        for (int t = 0; t < (BM * 8) / THREADS; t++) {
            int i  = tid + t * THREADS;
            int m  = i >> 3;
            int kq = i & 7;
            float4 v = make_float4(0.f, 0.f, 0.f, 0.f);
            if (m0 + m < M)
                v = *(const float4*)&A[(size_t)(m0 + m) * lda + k0 + kq * 4];
            uint4 u = make_uint4(f2t(v.x), f2t(v.y), f2t(v.z), f2t(v.w));
            *(uint4*)&As[m * SA + kq * 4] = u;
        }
        // ---- B tile ----
        if (BT) {   // B [N x K] -> Bs[n][k]
#pragma unroll
            for (int t = 0; t < (BN * 8) / THREADS; t++) {
                int i  = tid + t * THREADS;
                int n  = i >> 3;
                int kq = i & 7;
                float4 v = *(const float4*)&Bp[(size_t)(n0 + n) * ldb + k0 + kq * 4];
                uint4 u = make_uint4(f2t(v.x), f2t(v.y), f2t(v.z), f2t(v.w));
                *(uint4*)&Bs[n * SA + kq * 4] = u;
            }
        } else {    // B [K x N] -> Bs[k][n]
#pragma unroll
            for (int t = 0; t < (BK * BN / 4) / THREADS; t++) {
                int i  = tid + t * THREADS;
                int kk = i / (BN / 4);
                int nq = i % (BN / 4);
                float4 v = *(const float4*)&Bp[(size_t)(k0 + kk) * ldb + n0 + nq * 4];
                uint4 u = make_uint4(f2t(v.x), f2t(v.y), f2t(v.z), f2t(v.w));
                *(uint4*)&Bs[kk * SBN + nq * 4] = u;
            }
        }
        __syncthreads();

        // ---- compute: LDSM fragment loads ----
#pragma unroll
        for (int kk = 0; kk < BK; kk += 8) {
            unsigned af[4][4], bf[4][2];
            {
                int arow = rr + (sub & 1) * 8;
                int acol = kk + (sub >> 1) * 4;
#pragma unroll
                for (int i = 0; i < 4; i++) {
                    int row = wm * 64 + i * 16 + arow;
                    ldsm4(af[i], &As[row * SA + acol]);
                }
            }
            if (BT) {
                int brow = rr + (sub >> 1) * 8;
                int bcol = kk + (sub & 1) * 4;
#pragma unroll
                for (int jp = 0; jp < 2; jp++) {
                    int n = wn * 32 + jp * 16 + brow;
                    unsigned tmp[4];
                    ldsm4(tmp, &Bs[n * SA + bcol]);
                    bf[jp * 2][0]     = tmp[0];
                    bf[jp * 2][1]     = tmp[1];
                    bf[jp * 2 + 1][0] = tmp[2];
                    bf[jp * 2 + 1][1] = tmp[3];
                }
            } else {
#pragma unroll
                for (int j = 0; j < 4; j++) {
                    int c0 = wn * 32 + j * 8 + gid;
                    bf[j][0] = Bs[(kk + tig) * SBN + c0];
                    bf[j][1] = Bs[(kk + tig + 4) * SBN + c0];
                }
            }
#pragma unroll
            for (int i = 0; i < 4; i++)
#pragma unroll
                for (int j = 0; j < 4; j++)
                    mma_tf32(acc[i][j], af[i], bf[j]);
        }
        __syncthreads();
    }

    // ---- epilogue (N exact multiple of BN; only M ragged) ----
#pragma unroll
    for (int i = 0; i < 4; i++) {
        int rm = m0 + wm * 64 + i * 16 + gid;
#pragma unroll
        for (int j = 0; j < 4; j++) {
            int cn = n0 + wn * 32 + j * 8 + tig * 2;
            if (rm < M) {
                epi.store(bh, rm, cn,     acc[i][j][0]);
                epi.store(bh, rm, cn + 1, acc[i][j][1]);
            }
            if (rm + 8 < M) {
                epi.store(bh, rm + 8, cn,     acc[i][j][2]);
                epi.store(bh, rm + 8, cn + 1, acc[i][j][3]);
            }
        }
    }
}

// ---------------------------------------------------------------------------
// Small helper kernels
// ---------------------------------------------------------------------------
__global__ void pool_kernel()
{
    int idx = blockIdx.x * blockDim.x + threadIdx.x;
    if (idx >= BH * Ll * Dd) return;
    int d  = idx % Dd;
    int l  = (idx / Dd) % Ll;
    int bh = idx / (Dd * Ll);
    int lr = l / 16, lc = l % 16;
    float sq = 0.f, sk = 0.f;
#pragma unroll
    for (int r = 0; r < 2; r++)
#pragma unroll
        for (int c = 0; c < 2; c++) {
            int p = (2 * lr + r) * 32 + (2 * lc + c);
            size_t off = ((size_t)bh * NT + (p + 1)) * Dd + d;
            sq += g_q[off];
            sk += g_k[off];
        }
    g_qland[((size_t)bh * Ll + l) * Dd + d] = sq * 0.25f;
    g_kland[((size_t)bh * Ll + l) * Dd + d] = sk * 0.25f;
}

__device__ __forceinline__ float row_sq_norm(const float* p)
{
    const float4* p4 = (const float4*)p;
    float s = 0.f;
#pragma unroll
    for (int i = 0; i < Dd / 4; i++) {
        float4 v = p4[i];
        s += v.x * v.x + v.y * v.y + v.z * v.z + v.w * v.w;
    }
    return s;
}

__global__ void norms_patch_kernel()
{
    int idx = blockIdx.x * blockDim.x + threadIdx.x;
    if (idx >= BH * NP) return;
    int bh = idx / NP, p = idx % NP;
    size_t off = ((size_t)bh * NT + (p + 1)) * Dd;
    g_qpn[idx] = row_sq_norm(&g_q[off]);
    g_kpn[idx] = row_sq_norm(&g_k[off]);
}

__global__ void norms_land_kernel()
{
    int idx = blockIdx.x * blockDim.x + threadIdx.x;
    if (idx >= BH * Ll) return;
    g_qln[idx] = row_sq_norm(&g_qland[(size_t)idx * Dd]);
    g_kln[idx] = row_sq_norm(&g_kland[(size_t)idx * Dd]);
    if (idx < BH)
        g_qcn[idx] = row_sq_norm(&g_q[(size_t)idx * NT * Dd]);  // n = 0 (cls)
}

__global__ void newton_init_kernel()
{
    int bh = blockIdx.x;
    int t  = threadIdx.x;        // 256 threads, one row each
    const float* M2b = g_M2 + (size_t)bh * Ll * Ll;
    const float* row = M2b + (size_t)t * Ll;
    float rs = 0.f;
    for (int j = 0; j < Ll; j++) rs += fabsf(row[j]);
    __shared__ float red[256];
    red[t] = rs;
    __syncthreads();
    for (int s = 128; s > 0; s >>= 1) {
        if (t < s) red[t] = fmaxf(red[t], red[t + s]);
        __syncthreads();
    }
    float nrm = red[0];
    float scale = 1.0f / (nrm * nrm + 1e-6f);
    float* inv = g_invA + (size_t)bh * Ll * Ll;
    for (int idx = t; idx < Ll * Ll; idx += 256) {
        int i = idx / Ll, j = idx % Ll;
        inv[idx] = M2b[(size_t)j * Ll + i] * scale;
    }
}

__global__ void ycls_kernel()
{
    int bh = blockIdx.x;
    int t  = threadIdx.x;        // 256 threads
    __shared__ float sc[Ll];
    __shared__ float qc[Dd];
    if (t < Dd) qc[t] = g_q[(size_t)bh * NT * Dd + t];
    __syncthreads();
    const float* kl = g_kland + ((size_t)bh * Ll + t) * Dd;
    float dot = 0.f;
#pragma unroll
    for (int d = 0; d < Dd; d++) dot += qc[d] * kl[d];
    float dist = g_qcn[bh] + g_kln[(size_t)bh * Ll + t] - 2.0f * dot;
    sc[t] = fast_exp(dist * NEG_INV_TAU);
    __syncthreads();
    if (t < Dd) {
        float s = 0.f;
        for (int l = 0; l < Ll; l++)
            s += sc[l] * g_Vmix[((size_t)bh * Ll + l) * Dd + t];
        int b = bh / Hh, h = bh % Hh;
        g_attn[(size_t)b * NT * Cd + h * Dd + t] = s;
    }
}

// ---------------------------------------------------------------------------
// Host launcher
// ---------------------------------------------------------------------------
template<int BM, int BN, bool BT, class Epi>
static void launch_gemm(dim3 grid, const float* A, const float* Bp,
                        int M, int Nn, int K, int lda, int ldb,
                        size_t sA, size_t sB, Epi epi)
{
    constexpr int THREADS = (BM / 64) * (BN / 32) * 32;
    gemm_tc<BM, BN, BT, Epi><<<grid, THREADS>>>(
        A, Bp, M, Nn, K, lda, ldb, sA, sB, epi);
}

extern "C" void kernel_launch(void* const* d_in, const int* in_sizes, int n_in,
                              void* d_out, int out_size)
{
    (void)in_sizes; (void)n_in; (void)out_size;
    const float* x      = (const float*)d_in[0];
    const float* qkv_w  = (const float*)d_in[1];
    const float* qkv_b  = (const float*)d_in[2];
    const float* proj_w = (const float*)d_in[3];
    const float* proj_b = (const float*)d_in[4];
    float* out = (float*)d_out;

    float *p_q, *p_k, *p_v, *p_qland, *p_kland;
    float *p_qpn, *p_kpn, *p_qln, *p_kln;
    float *p_M1, *p_M2, *p_M3, *p_invA, *p_invB, *p_T, *p_KV, *p_Vmix, *p_attn;
    cudaGetSymbolAddress((void**)&p_q, g_q);
    cudaGetSymbolAddress((void**)&p_k, g_k);
    cudaGetSymbolAddress((void**)&p_v, g_v);
    cudaGetSymbolAddress((void**)&p_qland, g_qland);
    cudaGetSymbolAddress((void**)&p_kland, g_kland);
    cudaGetSymbolAddress((void**)&p_qpn, g_qpn);
    cudaGetSymbolAddress((void**)&p_kpn, g_kpn);
    cudaGetSymbolAddress((void**)&p_qln, g_qln);
    cudaGetSymbolAddress((void**)&p_kln, g_kln);
    cudaGetSymbolAddress((void**)&p_M1, g_M1);
    cudaGetSymbolAddress((void**)&p_M2, g_M2);
    cudaGetSymbolAddress((void**)&p_M3, g_M3);
    cudaGetSymbolAddress((void**)&p_invA, g_invA);
    cudaGetSymbolAddress((void**)&p_invB, g_invB);
    cudaGetSymbolAddress((void**)&p_T, g_T);
    cudaGetSymbolAddress((void**)&p_KV, g_KV);
    cudaGetSymbolAddress((void**)&p_Vmix, g_Vmix);
    cudaGetSymbolAddress((void**)&p_attn, g_attn);

    const int M_tok = Bn * NT;   // 16400
    const int gy_tok = (M_tok + 127) / 128;

    // 1. QKV projection: x @ qkv_w^T + b, scattered into q/k/v [B][H][N][D]
    launch_gemm<128, 128, true>(dim3(3 * Cd / 128, gy_tok, 1),
        x, qkv_w, M_tok, 3 * Cd, Cd, Cd, Cd, 0, 0, EpiQKV{qkv_b});

    // 2. pooling + norms
    pool_kernel<<<(BH * Ll * Dd + 255) / 256, 256>>>();
    norms_patch_kernel<<<(BH * NP + 255) / 256, 256>>>();
    norms_land_kernel<<<(BH * Ll + 255) / 256, 256>>>();

    // 3. Gauss kernel matrices
    launch_gemm<128, 128, true>(dim3(Ll / 128, Ll / 128, BH),       // M2
        p_qland, p_kland, Ll, Ll, Dd, Dd, Dd,
        (size_t)Ll * Dd, (size_t)Ll * Dd,
        EpiGauss{p_qln, p_kln, p_M2, Ll, Ll, Ll, (size_t)Ll * Ll});
    launch_gemm<128, 128, true>(dim3(Ll / 128, NP / 128, BH),       // M1
        p_q + Dd, p_kland, NP, Ll, Dd, Dd, Dd,
        (size_t)NT * Dd, (size_t)Ll * Dd,
        EpiGauss{p_qpn, p_kln, p_M1, NP, Ll, Ll, (size_t)NP * Ll});
    launch_gemm<128, 128, true>(dim3(NP / 128, Ll / 128, BH),       // M3
        p_qland, p_k + Dd, Ll, NP, Dd, Dd, Dd,
        (size_t)Ll * Dd, (size_t)NT * Dd,
        EpiGauss{p_qln, p_kpn, p_M3, Ll, NP, NP, (size_t)Ll * NP});

    // 4. Newton iterations for M2^-1
    newton_init_kernel<<<BH, 256>>>();
    {
        float* cur = p_invA;
        float* nxt = p_invB;
        dim3 grid(Ll / 128, Ll / 128, BH);
        for (int it = 0; it < NEWTON_ITERS; it++) {
            launch_gemm<128, 128, false>(grid,
                p_M2, cur, Ll, Ll, Ll, Ll, Ll,
                (size_t)Ll * Ll, (size_t)Ll * Ll,
                EpiPlain{p_T, Ll, (size_t)Ll * Ll});
            launch_gemm<128, 128, false>(grid,
                cur, p_T, Ll, Ll, Ll, Ll, Ll,
                (size_t)Ll * Ll, (size_t)Ll * Ll,
                EpiNewton{cur, nxt});
            float* tmp = cur; cur = nxt; nxt = tmp;
        }
        // NEWTON_ITERS even -> result in p_invA
    }

    // 5. KV = M3 @ v_patch : [L x D]
    launch_gemm<128, 64, false>(dim3(1, Ll / 128, BH),
        p_M3, p_v + Dd, Ll, Dd, NP, NP, Dd,
        (size_t)Ll * NP, (size_t)NT * Dd,
        EpiPlain{p_KV, Dd, (size_t)Ll * Dd});
    // 6. V_mixed = M2_inv @ KV : [L x D]
    launch_gemm<128, 64, false>(dim3(1, Ll / 128, BH),
        p_invA, p_KV, Ll, Dd, Ll, Ll, Dd,
        (size_t)Ll * Ll, (size_t)Ll * Dd,
        EpiPlain{p_Vmix, Dd, (size_t)Ll * Dd});
    // 7. y_patch = M1 @ V_mixed -> attn[b][1..1024][h*64+d]
    launch_gemm<128, 64, false>(dim3(1, NP / 128, BH),
        p_M1, p_Vmix, NP, Dd, Ll, Ll, Dd,
        (size_t)NP * Ll, (size_t)Ll * Dd, EpiYPatch{});
    // 8. y_cls -> attn[b][0][h*64+d]
    ycls_kernel<<<BH, 256>>>();

    // 9. output projection: attn @ proj_w^T + proj_b
    launch_gemm<128, 128, true>(dim3(Cd / 128, gy_tok, 1),
        p_attn, proj_w, M_tok, Cd, Cd, Cd, Cd, 0, 0, EpiProj{proj_b, out});
}

// round 12
// speedup vs baseline: 1.6872x; 1.1253x over previous
#include <cuda_runtime.h>
#include <cuda_fp16.h>
#include <math.h>
#include <stddef.h>
#include <stdint.h>

// ---------------------------------------------------------------------------
// Problem constants
// ---------------------------------------------------------------------------
#define Bn   16
#define NT   1025            // tokens (1 cls + 1024 patches)
#define Cd   768
#define Hh   12
#define Dd   64
#define NP   1024            // patch tokens
#define Ll   256             // landmarks (16x16)
#define BH   (Bn*Hh)         // 192
#define NEWTON_ITERS 6
#define NEG_INV_TAU (-0.125f)   // tau = sqrt(64) = 8

// ---------------------------------------------------------------------------
// Scratch (static device globals)
// ---------------------------------------------------------------------------
__device__ float g_q[BH * NT * Dd];
__device__ float g_k[BH * NT * Dd];
__device__ float g_v[BH * NT * Dd];
__device__ float g_qland[BH * Ll * Dd];
__device__ float g_kland[BH * Ll * Dd];
__device__ float g_qpn[BH * NP];
__device__ float g_kpn[BH * NP];
__device__ float g_qln[BH * Ll];
__device__ float g_kln[BH * Ll];
__device__ float g_qcn[BH];
__device__ float g_M1[(size_t)BH * NP * Ll];
__device__ float g_M2[(size_t)BH * Ll * Ll];
__device__ float g_M3[(size_t)BH * Ll * NP];
__device__ float g_invA[(size_t)BH * Ll * Ll];
__device__ float g_invB[(size_t)BH * Ll * Ll];
__device__ float g_T[(size_t)BH * Ll * Ll];
__device__ float g_KV[BH * Ll * Dd];
__device__ float g_Vmix[BH * Ll * Dd];
__device__ float g_attn[(size_t)Bn * NT * Cd];

// ---------------------------------------------------------------------------
// Fast exp on FMA/ALU pipes (no MUFU).
// ---------------------------------------------------------------------------
__device__ __forceinline__ float fast_exp(float x)
{
    float y  = x * 1.4426950408889634f;       // log2(e)
    int   ni = __float2int_rn(y);
    float nf = (float)ni;
    float f  = y - nf;                        // [-0.5, 0.5]
    float p = 1.3333558146e-3f;
    p = fmaf(p, f, 9.6181291076e-3f);
    p = fmaf(p, f, 5.5504108664e-2f);
    p = fmaf(p, f, 2.4022650696e-1f);
    p = fmaf(p, f, 6.9314718056e-1f);
    p = fmaf(p, f, 1.0f);
    return __int_as_float(__float_as_int(p) + (ni << 23));
}

// ---------------------------------------------------------------------------
// Epilogue functors
// ---------------------------------------------------------------------------
struct EpiQKV {
    const float* bias;
    __device__ __forceinline__ void store(int, int m, int j, float acc) const {
        int b = m / NT, n = m % NT;
        int part = j / Cd;
        int rem  = j % Cd;
        int h = rem / Dd, d = rem % Dd;
        float* dst = (part == 0) ? g_q : ((part == 1) ? g_k : g_v);
        dst[(((size_t)b * Hh + h) * NT + n) * Dd + d] = acc + bias[j];
    }
};

struct EpiGauss {
    const float* xn; const float* yn; float* out;
    int sxn; int syn; int ldc; size_t sout;
    __device__ __forceinline__ void store(int bh, int m, int n, float acc) const {
        float dist = xn[(size_t)bh * sxn + m] + yn[(size_t)bh * syn + n] - 2.0f * acc;
        out[(size_t)bh * sout + (size_t)m * ldc + n] = fast_exp(dist * NEG_INV_TAU);
    }
};

struct EpiPlain {
    float* out; int ldc; size_t s;
    __device__ __forceinline__ void store(int bh, int m, int n, float acc) const {
        out[(size_t)bh * s + (size_t)m * ldc + n] = acc;
    }
};

struct EpiNewton {   // out = 2*inv - acc
    const float* inv; float* out;
    __device__ __forceinline__ void store(int bh, int m, int n, float acc) const {
        size_t off = ((size_t)bh * Ll + m) * Ll + n;
        out[off] = 2.0f * inv[off] - acc;
    }
};

struct EpiYPatch {
    __device__ __forceinline__ void store(int bh, int m, int j, float acc) const {
        int b = bh / Hh, h = bh % Hh;
        g_attn[((size_t)b * NT + (m + 1)) * Cd + h * Dd + j] = acc;
    }
};

struct EpiProj {
    const float* bias; float* out;
    __device__ __forceinline__ void store(int, int m, int j, float acc) const {
        out[(size_t)m * Cd + j] = acc + bias[j];
    }
};

// ---------------------------------------------------------------------------
// fp16 MMA helpers
// ---------------------------------------------------------------------------
__device__ __forceinline__ unsigned pack2h(float a, float b) {
    __half2 h = __floats2half2_rn(a, b);      // lo = a, hi = b
    return *(unsigned*)&h;
}

__device__ __forceinline__ void mma_f16(float* c, const unsigned* a, const unsigned* b) {
    asm volatile(
        "mma.sync.aligned.m16n8k16.row.col.f32.f16.f16.f32 "
        "{%0,%1,%2,%3}, {%4,%5,%6,%7}, {%8,%9}, {%0,%1,%2,%3};"
        : "+f"(c[0]), "+f"(c[1]), "+f"(c[2]), "+f"(c[3])
        : "r"(a[0]), "r"(a[1]), "r"(a[2]), "r"(a[3]), "r"(b[0]), "r"(b[1]));
}

__device__ __forceinline__ void ldsm4h(unsigned* r, const __half* p) {
    unsigned a = (unsigned)__cvta_generic_to_shared((void*)p);
    asm volatile("ldmatrix.sync.aligned.m8n8.x4.shared.b16 {%0,%1,%2,%3}, [%4];"
                 : "=r"(r[0]), "=r"(r[1]), "=r"(r[2]), "=r"(r[3]) : "r"(a));
}

__device__ __forceinline__ void ldsm4h_t(unsigned* r, const __half* p) {
    unsigned a = (unsigned)__cvta_generic_to_shared((void*)p);
    asm volatile("ldmatrix.sync.aligned.m8n8.x4.trans.shared.b16 {%0,%1,%2,%3}, [%4];"
                 : "=r"(r[0]), "=r"(r[1]), "=r"(r[2]), "=r"(r[3]) : "r"(a));
}

// ---------------------------------------------------------------------------
// Synchronous fp16 tensor-core GEMM (R8/R9 structure, fp16 m16n8k16 path).
//   C = A(MxK, row-major, lda) @ op(B)
//   BT=true : B is [N x K] row-major (C = A @ B^T)
//   BT=false: B is [K x N] row-major (C = A @ B)
// smem holds fp16 (cvt once at store); fragments via ldmatrix.b16 (A, BT-B
// plain x4; non-BT B x4.trans does the k-major -> n-major transpose in HW).
// Requires: K % 32 == 0, Nn % BN == 0, lda/ldb % 4 == 0. M may be ragged.
// ---------------------------------------------------------------------------
template<int BM, int BN, bool BT, class Epi>
__global__ void __launch_bounds__((BM / 64) * (BN / 32) * 32)
gemm_tc(const float* __restrict__ A, const float* __restrict__ Bp,
        int M, int Nn, int K, int lda, int ldb,
        size_t sA, size_t sB, Epi epi)
{
    constexpr int BK = 32;
    constexpr int WARPS_M = BM / 64;
    constexpr int WARPS_N = BN / 32;
    constexpr int THREADS = WARPS_M * WARPS_N * 32;
    constexpr int SAH  = BK + 8;     // A / BT-B row stride (halfs): 80 B rows
    constexpr int SBNH = BN + 8;     // non-BT B row stride (halfs)

    __shared__ __align__(16) __half As[BM * SAH];
    __shared__ __align__(16) __half Bs[BT ? (BN * SAH) : (BK * SBNH)];

    const int bh = blockIdx.z;
    A  += (size_t)bh * sA;
    Bp += (size_t)bh * sB;
    const int m0 = blockIdx.y * BM;
    const int n0 = blockIdx.x * BN;
    const int tid  = threadIdx.x;
    const int lane = tid & 31;
    const int warp = tid >> 5;
    const int wm = warp / WARPS_N;
    const int wn = warp % WARPS_N;
    const int gid = lane >> 2;      // 0..7
    const int tig = lane & 3;       // 0..3
    const int rr  = lane & 7;       // ldmatrix row within 8-group
    const int sub = lane >> 3;      // ldmatrix sub-matrix id 0..3

    float acc[4][4][4];
#pragma unroll
    for (int i = 0; i < 4; i++)
#pragma unroll
        for (int j = 0; j < 4; j++)
#pragma unroll
            for (int r = 0; r < 4; r++) acc[i][j][r] = 0.0f;

    for (int k0 = 0; k0 < K; k0 += BK) {
        // ---- A tile -> As[m][k] fp16 ----
#pragma unroll
        for (int t = 0; t < (BM * 8) / THREADS; t++) {
            int i  = tid + t * THREADS;
            int m  = i >> 3;
            int kq = i & 7;
            float4 v = make_float4(0.f, 0.f, 0.f, 0.f);
            if (m0 + m < M)
                v = *(const float4*)&A[(size_t)(m0 + m) * lda + k0 + kq * 4];
            uint2 u = make_uint2(pack2h(v.x, v.y), pack2h(v.z, v.w));
            *(uint2*)&As[m * SAH + kq * 4] = u;
        }
        // ---- B tile ----
        if (BT) {   // B [N x K] -> Bs[n][k]
#pragma unroll
            for (int t = 0; t < (BN * 8) / THREADS; t++) {
                int i  = tid + t * THREADS;
                int n  = i >> 3;
                int kq = i & 7;
                float4 v = *(const float4*)&Bp[(size_t)(n0 + n) * ldb + k0 + kq * 4];
                uint2 u = make_uint2(pack2h(v.x, v.y), pack2h(v.z, v.w));
                *(uint2*)&Bs[n * SAH + kq * 4] = u;
            }
        } else {    // B [K x N] -> Bs[k][n]
#pragma unroll
            for (int t = 0; t < (BK * BN / 4) / THREADS; t++) {
                int i  = tid + t * THREADS;
                int kk = i / (BN / 4);
                int nq = i % (BN / 4);
                float4 v = *(const float4*)&Bp[(size_t)(k0 + kk) * ldb + n0 + nq * 4];
                uint2 u = make_uint2(pack2h(v.x, v.y), pack2h(v.z, v.w));
                *(uint2*)&Bs[kk * SBNH + nq * 4] = u;
            }
        }
        __syncthreads();

        // ---- compute: 2 x k16 steps per BK=32 ----
#pragma unroll
        for (int kk = 0; kk < BK; kk += 16) {
            unsigned af[4][4], bf[4][2];
            // A: one ldmatrix.x4 per 16-row block covers m16 x k16
            {
                int arow = rr + (sub & 1) * 8;
                int acol = kk + (sub >> 1) * 8;
#pragma unroll
                for (int i = 0; i < 4; i++) {
                    int row = wm * 64 + i * 16 + arow;
                    ldsm4h(af[i], &As[row * SAH + acol]);
                }
            }
            if (BT) {
                // one ldmatrix.x4 covers n16 x k16 -> two B fragments
                int brow = rr + (sub & 1) * 8;
                int bcol = kk + (sub >> 1) * 8;
#pragma unroll
                for (int jp = 0; jp < 2; jp++) {
                    int n = wn * 32 + jp * 16 + brow;
                    unsigned tmp[4];
                    ldsm4h(tmp, &Bs[n * SAH + bcol]);
                    bf[jp * 2][0]     = tmp[0];   // n0-7,  k0-7
                    bf[jp * 2][1]     = tmp[2];   // n0-7,  k8-15
                    bf[jp * 2 + 1][0] = tmp[1];   // n8-15, k0-7
                    bf[jp * 2 + 1][1] = tmp[3];   // n8-15, k8-15
                }
            } else {
                // trans ldmatrix.x4 on [k][n] covers k16 x n16 -> two fragments
                int krow = kk + (sub & 1) * 8 + rr;
#pragma unroll
                for (int jp = 0; jp < 2; jp++) {
                    int ncol = wn * 32 + jp * 16 + (sub >> 1) * 8;
                    unsigned tmp[4];
                    ldsm4h_t(tmp, &Bs[krow * SBNH + ncol]);
                    bf[jp * 2][0]     = tmp[0];   // n0-7,  k0-7
                    bf[jp * 2][1]     = tmp[1];   // n0-7,  k8-15
                    bf[jp * 2 + 1][0] = tmp[2];   // n8-15, k0-7
                    bf[jp * 2 + 1][1] = tmp[3];   // n8-15, k8-15
                }
            }
#pragma unroll
            for (int i = 0; i < 4; i++)
#pragma unroll
                for (int j = 0; j < 4; j++)
                    mma_f16(acc[i][j], af[i], bf[j]);
        }
        __syncthreads();
    }

    // ---- epilogue (N exact multiple of BN; only M ragged) ----
#pragma unroll
    for (int i = 0; i < 4; i++) {
        int rm = m0 + wm * 64 + i * 16 + gid;
#pragma unroll
        for (int j = 0; j < 4; j++) {
            int cn = n0 + wn * 32 + j * 8 + tig * 2;
            if (rm < M) {
                epi.store(bh, rm, cn,     acc[i][j][0]);
                epi.store(bh, rm, cn + 1, acc[i][j][1]);
            }
            if (rm + 8 < M) {
                epi.store(bh, rm + 8, cn,     acc[i][j][2]);
                epi.store(bh, rm + 8, cn + 1, acc[i][j][3]);
            }
        }
    }
}

// ---------------------------------------------------------------------------
// Small helper kernels
// ---------------------------------------------------------------------------
__global__ void pool_kernel()
{
    int idx = blockIdx.x * blockDim.x + threadIdx.x;
    if (idx >= BH * Ll * Dd) return;
    int d  = idx % Dd;
    int l  = (idx / Dd) % Ll;
    int bh = idx / (Dd * Ll);
    int lr = l / 16, lc = l % 16;
    float sq = 0.f, sk = 0.f;
#pragma unroll
    for (int r = 0; r < 2; r++)
#pragma unroll
        for (int c = 0; c < 2; c++) {
            int p = (2 * lr + r) * 32 + (2 * lc + c);
            size_t off = ((size_t)bh * NT + (p + 1)) * Dd + d;
            sq += g_q[off];
            sk += g_k[off];
        }
    g_qland[((size_t)bh * Ll + l) * Dd + d] = sq * 0.25f;
    g_kland[((size_t)bh * Ll + l) * Dd + d] = sk * 0.25f;
}

__device__ __forceinline__ float row_sq_norm(const float* p)
{
    const float4* p4 = (const float4*)p;
    float s = 0.f;
#pragma unroll
    for (int i = 0; i < Dd / 4; i++) {
        float4 v = p4[i];
        s += v.x * v.x + v.y * v.y + v.z * v.z + v.w * v.w;
    }
    return s;
}

__global__ void norms_patch_kernel()
{
    int idx = blockIdx.x * blockDim.x + threadIdx.x;
    if (idx >= BH * NP) return;
    int bh = idx / NP, p = idx % NP;
    size_t off = ((size_t)bh * NT + (p + 1)) * Dd;
    g_qpn[idx] = row_sq_norm(&g_q[off]);
    g_kpn[idx] = row_sq_norm(&g_k[off]);
}

__global__ void norms_land_kernel()
{
    int idx = blockIdx.x * blockDim.x + threadIdx.x;
    if (idx >= BH * Ll) return;
    g_qln[idx] = row_sq_norm(&g_qland[(size_t)idx * Dd]);
    g_kln[idx] = row_sq_norm(&g_kland[(size_t)idx * Dd]);
    if (idx < BH)
        g_qcn[idx] = row_sq_norm(&g_q[(size_t)idx * NT * Dd]);  // n = 0 (cls)
}

__global__ void newton_init_kernel()
{
    int bh = blockIdx.x;
    int t  = threadIdx.x;
    const float* M2b = g_M2 + (size_t)bh * Ll * Ll;
    const float* row = M2b + (size_t)t * Ll;
    float rs = 0.f;
    for (int j = 0; j < Ll; j++) rs += fabsf(row[j]);
    __shared__ float red[256];
    red[t] = rs;
    __syncthreads();
    for (int s = 128; s > 0; s >>= 1) {
        if (t < s) red[t] = fmaxf(red[t], red[t + s]);
        __syncthreads();
    }
    float nrm = red[0];
    float scale = 1.0f / (nrm * nrm + 1e-6f);
    float* inv = g_invA + (size_t)bh * Ll * Ll;
    for (int idx = t; idx < Ll * Ll; idx += 256) {
        int i = idx / Ll, j = idx % Ll;
        inv[idx] = M2b[(size_t)j * Ll + i] * scale;
    }
}

__global__ void ycls_kernel()
{
    int bh = blockIdx.x;
    int t  = threadIdx.x;
    __shared__ float sc[Ll];
    __shared__ float qc[Dd];
    if (t < Dd) qc[t] = g_q[(size_t)bh * NT * Dd + t];
    __syncthreads();
    const float* kl = g_kland + ((size_t)bh * Ll + t) * Dd;
    float dot = 0.f;
#pragma unroll
    for (int d = 0; d < Dd; d++) dot += qc[d] * kl[d];
    float dist = g_qcn[bh] + g_kln[(size_t)bh * Ll + t] - 2.0f * dot;
    sc[t] = fast_exp(dist * NEG_INV_TAU);
    __syncthreads();
    if (t < Dd) {
        float s = 0.f;
        for (int l = 0; l < Ll; l++)
            s += sc[l] * g_Vmix[((size_t)bh * Ll + l) * Dd + t];
        int b = bh / Hh, h = bh % Hh;
        g_attn[(size_t)b * NT * Cd + h * Dd + t] = s;
    }
}

// ---------------------------------------------------------------------------
// Host launcher
// ---------------------------------------------------------------------------
template<int BM, int BN, bool BT, class Epi>
static void launch_gemm(dim3 grid, const float* A, const float* Bp,
                        int M, int Nn, int K, int lda, int ldb,
                        size_t sA, size_t sB, Epi epi)
{
    constexpr int THREADS = (BM / 64) * (BN / 32) * 32;
    gemm_tc<BM, BN, BT, Epi><<<grid, THREADS>>>(
        A, Bp, M, Nn, K, lda, ldb, sA, sB, epi);
}

extern "C" void kernel_launch(void* const* d_in, const int* in_sizes, int n_in,
                              void* d_out, int out_size)
{
    (void)in_sizes; (void)n_in; (void)out_size;
    const float* x      = (const float*)d_in[0];
    const float* qkv_w  = (const float*)d_in[1];
    const float* qkv_b  = (const float*)d_in[2];
    const float* proj_w = (const float*)d_in[3];
    const float* proj_b = (const float*)d_in[4];
    float* out = (float*)d_out;

    float *p_q, *p_k, *p_v, *p_qland, *p_kland;
    float *p_qpn, *p_kpn, *p_qln, *p_kln;
    float *p_M1, *p_M2, *p_M3, *p_invA, *p_invB, *p_T, *p_KV, *p_Vmix, *p_attn;
    cudaGetSymbolAddress((void**)&p_q, g_q);
    cudaGetSymbolAddress((void**)&p_k, g_k);
    cudaGetSymbolAddress((void**)&p_v, g_v);
    cudaGetSymbolAddress((void**)&p_qland, g_qland);
    cudaGetSymbolAddress((void**)&p_kland, g_kland);
    cudaGetSymbolAddress((void**)&p_qpn, g_qpn);
    cudaGetSymbolAddress((void**)&p_kpn, g_kpn);
    cudaGetSymbolAddress((void**)&p_qln, g_qln);
    cudaGetSymbolAddress((void**)&p_kln, g_kln);
    cudaGetSymbolAddress((void**)&p_M1, g_M1);
    cudaGetSymbolAddress((void**)&p_M2, g_M2);
    cudaGetSymbolAddress((void**)&p_M3, g_M3);
    cudaGetSymbolAddress((void**)&p_invA, g_invA);
    cudaGetSymbolAddress((void**)&p_invB, g_invB);
    cudaGetSymbolAddress((void**)&p_T, g_T);
    cudaGetSymbolAddress((void**)&p_KV, g_KV);
    cudaGetSymbolAddress((void**)&p_Vmix, g_Vmix);
    cudaGetSymbolAddress((void**)&p_attn, g_attn);

    const int M_tok = Bn * NT;   // 16400
    const int gy_tok = (M_tok + 127) / 128;

    // 1. QKV projection
    launch_gemm<128, 128, true>(dim3(3 * Cd / 128, gy_tok, 1),
        x, qkv_w, M_tok, 3 * Cd, Cd, Cd, Cd, 0, 0, EpiQKV{qkv_b});

    // 2. pooling + norms
    pool_kernel<<<(BH * Ll * Dd + 255) / 256, 256>>>();
    norms_patch_kernel<<<(BH * NP + 255) / 256, 256>>>();
    norms_land_kernel<<<(BH * Ll + 255) / 256, 256>>>();

    // 3. Gauss kernel matrices
    launch_gemm<128, 128, true>(dim3(Ll / 128, Ll / 128, BH),       // M2
        p_qland, p_kland, Ll, Ll, Dd, Dd, Dd,
        (size_t)Ll * Dd, (size_t)Ll * Dd,
        EpiGauss{p_qln, p_kln, p_M2, Ll, Ll, Ll, (size_t)Ll * Ll});
    launch_gemm<128, 128, true>(dim3(Ll / 128, NP / 128, BH),       // M1
        p_q + Dd, p_kland, NP, Ll, Dd, Dd, Dd,
        (size_t)NT * Dd, (size_t)Ll * Dd,
        EpiGauss{p_qpn, p_kln, p_M1, NP, Ll, Ll, (size_t)NP * Ll});
    launch_gemm<128, 128, true>(dim3(NP / 128, Ll / 128, BH),       // M3
        p_qland, p_k + Dd, Ll, NP, Dd, Dd, Dd,
        (size_t)Ll * Dd, (size_t)NT * Dd,
        EpiGauss{p_qln, p_kpn, p_M3, Ll, NP, NP, (size_t)Ll * NP});

    // 4. Newton iterations for M2^-1
    newton_init_kernel<<<BH, 256>>>();
    {
        float* cur = p_invA;
        float* nxt = p_invB;
        dim3 grid(Ll / 128, Ll / 128, BH);
        for (int it = 0; it < NEWTON_ITERS; it++) {
            launch_gemm<128, 128, false>(grid,
                p_M2, cur, Ll, Ll, Ll, Ll, Ll,
                (size_t)Ll * Ll, (size_t)Ll * Ll,
                EpiPlain{p_T, Ll, (size_t)Ll * Ll});
            launch_gemm<128, 128, false>(grid,
                cur, p_T, Ll, Ll, Ll, Ll, Ll,
                (size_t)Ll * Ll, (size_t)Ll * Ll,
                EpiNewton{cur, nxt});
            float* tmp = cur; cur = nxt; nxt = tmp;
        }
        // NEWTON_ITERS even -> result in p_invA
    }

    // 5. KV = M3 @ v_patch : [L x D]
    launch_gemm<128, 64, false>(dim3(1, Ll / 128, BH),
        p_M3, p_v + Dd, Ll, Dd, NP, NP, Dd,
        (size_t)Ll * NP, (size_t)NT * Dd,
        EpiPlain{p_KV, Dd, (size_t)Ll * Dd});
    // 6. V_mixed = M2_inv @ KV : [L x D]
    launch_gemm<128, 64, false>(dim3(1, Ll / 128, BH),
        p_invA, p_KV, Ll, Dd, Ll, Ll, Dd,
        (size_t)Ll * Ll, (size_t)Ll * Dd,
        EpiPlain{p_Vmix, Dd, (size_t)Ll * Dd});
    // 7. y_patch = M1 @ V_mixed
    launch_gemm<128, 64, false>(dim3(1, NP / 128, BH),
        p_M1, p_Vmix, NP, Dd, Ll, Ll, Dd,
        (size_t)NP * Ll, (size_t)Ll * Dd, EpiYPatch{});
    // 8. y_cls
    ycls_kernel<<<BH, 256>>>();

    // 9. output projection
    launch_gemm<128, 128, true>(dim3(Cd / 128, gy_tok, 1),
        p_attn, proj_w, M_tok, Cd, Cd, Cd, Cd, 0, 0, EpiProj{proj_b, out});
}

// round 13
// speedup vs baseline: 1.9277x; 1.1425x over previous
#include <cuda_runtime.h>
#include <cuda_fp16.h>
#include <math.h>
#include <stddef.h>
#include <stdint.h>

// ---------------------------------------------------------------------------
// Problem constants
// ---------------------------------------------------------------------------
#define Bn   16
#define NT   1025            // tokens (1 cls + 1024 patches)
#define Cd   768
#define Hh   12
#define Dd   64
#define NP   1024            // patch tokens
#define Ll   256             // landmarks (16x16)
#define BH   (Bn*Hh)         // 192
#define NEWTON_ITERS 6
#define NEG_INV_TAU (-0.125f)   // tau = sqrt(64) = 8

// ---------------------------------------------------------------------------
// Scratch (static device globals) — intermediates in fp16, norms in fp32
// ---------------------------------------------------------------------------
__device__ __align__(16) __half g_q[BH * NT * Dd];
__device__ __align__(16) __half g_k[BH * NT * Dd];
__device__ __align__(16) __half g_v[BH * NT * Dd];
__device__ __align__(16) __half g_qland[BH * Ll * Dd];
__device__ __align__(16) __half g_kland[BH * Ll * Dd];
__device__ float g_qpn[BH * NP];
__device__ float g_kpn[BH * NP];
__device__ float g_qln[BH * Ll];
__device__ float g_kln[BH * Ll];
__device__ float g_qcn[BH];
__device__ __align__(16) __half g_M1[(size_t)BH * NP * Ll];
__device__ __align__(16) __half g_M2[(size_t)BH * Ll * Ll];
__device__ __align__(16) __half g_M3[(size_t)BH * Ll * NP];
__device__ __align__(16) __half g_invA[(size_t)BH * Ll * Ll];
__device__ __align__(16) __half g_invB[(size_t)BH * Ll * Ll];
__device__ __align__(16) __half g_T[(size_t)BH * Ll * Ll];
__device__ __align__(16) __half g_KV[BH * Ll * Dd];
__device__ __align__(16) __half g_Vmix[BH * Ll * Dd];
__device__ __align__(16) __half g_attn[(size_t)Bn * NT * Cd];

// ---------------------------------------------------------------------------
// Fast exp on FMA/ALU pipes (no MUFU).
// ---------------------------------------------------------------------------
__device__ __forceinline__ float fast_exp(float x)
{
    float y  = x * 1.4426950408889634f;       // log2(e)
    int   ni = __float2int_rn(y);
    float nf = (float)ni;
    float f  = y - nf;                        // [-0.5, 0.5]
    float p = 1.3333558146e-3f;
    p = fmaf(p, f, 9.6181291076e-3f);
    p = fmaf(p, f, 5.5504108664e-2f);
    p = fmaf(p, f, 2.4022650696e-1f);
    p = fmaf(p, f, 6.9314718056e-1f);
    p = fmaf(p, f, 1.0f);
    return __int_as_float(__float_as_int(p) + (ni << 23));
}

// ---------------------------------------------------------------------------
// Epilogue functors
// ---------------------------------------------------------------------------
struct EpiQKV {
    const float* bias;
    __device__ __forceinline__ void store(int, int m, int j, float acc) const {
        int b = m / NT, n = m % NT;
        int part = j / Cd;
        int rem  = j % Cd;
        int h = rem / Dd, d = rem % Dd;
        __half* dst = (part == 0) ? g_q : ((part == 1) ? g_k : g_v);
        dst[(((size_t)b * Hh + h) * NT + n) * Dd + d] = __float2half_rn(acc + bias[j]);
    }
};

struct EpiGauss {
    const float* xn; const float* yn; __half* out;
    int sxn; int syn; int ldc; size_t sout;
    __device__ __forceinline__ void store(int bh, int m, int n, float acc) const {
        float dist = xn[(size_t)bh * sxn + m] + yn[(size_t)bh * syn + n] - 2.0f * acc;
        out[(size_t)bh * sout + (size_t)m * ldc + n] =
            __float2half_rn(fast_exp(dist * NEG_INV_TAU));
    }
};

struct EpiPlainH {
    __half* out; int ldc; size_t s;
    __device__ __forceinline__ void store(int bh, int m, int n, float acc) const {
        out[(size_t)bh * s + (size_t)m * ldc + n] = __float2half_rn(acc);
    }
};

struct EpiNewton {   // out = 2*inv - acc
    const __half* inv; __half* out;
    __device__ __forceinline__ void store(int bh, int m, int n, float acc) const {
        size_t off = ((size_t)bh * Ll + m) * Ll + n;
        out[off] = __float2half_rn(2.0f * __half2float(inv[off]) - acc);
    }
};

struct EpiYPatch {
    __device__ __forceinline__ void store(int bh, int m, int j, float acc) const {
        int b = bh / Hh, h = bh % Hh;
        g_attn[((size_t)b * NT + (m + 1)) * Cd + h * Dd + j] = __float2half_rn(acc);
    }
};

struct EpiProj {
    const float* bias; float* out;
    __device__ __forceinline__ void store(int, int m, int j, float acc) const {
        out[(size_t)m * Cd + j] = acc + bias[j];
    }
};

// ---------------------------------------------------------------------------
// fp16 MMA helpers
// ---------------------------------------------------------------------------
__device__ __forceinline__ unsigned pack2h(float a, float b) {
    __half2 h = __floats2half2_rn(a, b);      // lo = a, hi = b
    return *(unsigned*)&h;
}

// load 4 consecutive elements, return 4 packed halfs
__device__ __forceinline__ uint2 ld4h(const float* p) {
    float4 v = *(const float4*)p;
    return make_uint2(pack2h(v.x, v.y), pack2h(v.z, v.w));
}
__device__ __forceinline__ uint2 ld4h(const __half* p) {
    return *(const uint2*)p;
}

__device__ __forceinline__ void mma_f16(float* c, const unsigned* a, const unsigned* b) {
    asm volatile(
        "mma.sync.aligned.m16n8k16.row.col.f32.f16.f16.f32 "
        "{%0,%1,%2,%3}, {%4,%5,%6,%7}, {%8,%9}, {%0,%1,%2,%3};"
        : "+f"(c[0]), "+f"(c[1]), "+f"(c[2]), "+f"(c[3])
        : "r"(a[0]), "r"(a[1]), "r"(a[2]), "r"(a[3]), "r"(b[0]), "r"(b[1]));
}

__device__ __forceinline__ void ldsm4h(unsigned* r, const __half* p) {
    unsigned a = (unsigned)__cvta_generic_to_shared((void*)p);
    asm volatile("ldmatrix.sync.aligned.m8n8.x4.shared.b16 {%0,%1,%2,%3}, [%4];"
                 : "=r"(r[0]), "=r"(r[1]), "=r"(r[2]), "=r"(r[3]) : "r"(a));
}

__device__ __forceinline__ void ldsm4h_t(unsigned* r, const __half* p) {
    unsigned a = (unsigned)__cvta_generic_to_shared((void*)p);
    asm volatile("ldmatrix.sync.aligned.m8n8.x4.trans.shared.b16 {%0,%1,%2,%3}, [%4];"
                 : "=r"(r[0]), "=r"(r[1]), "=r"(r[2]), "=r"(r[3]) : "r"(a));
}

// ---------------------------------------------------------------------------
// Synchronous fp16 tensor-core GEMM (R12 structure; typed operands TA/TB —
// fp16 inputs skip conversion entirely in the loader).
//   C = A(MxK, row-major, lda) @ op(B)
//   BT=true : B is [N x K] row-major (C = A @ B^T)
//   BT=false: B is [K x N] row-major (C = A @ B)
// Requires: K % 32 == 0, Nn % BN == 0, lda/ldb % 4 == 0. M may be ragged.
// ---------------------------------------------------------------------------
template<int BM, int BN, bool BT, class TA, class TB, class Epi>
__global__ void __launch_bounds__((BM / 64) * (BN / 32) * 32)
gemm_tc(const TA* __restrict__ A, const TB* __restrict__ Bp,
        int M, int Nn, int K, int lda, int ldb,
        size_t sA, size_t sB, Epi epi)
{
    constexpr int BK = 32;
    constexpr int WARPS_M = BM / 64;
    constexpr int WARPS_N = BN / 32;
    constexpr int THREADS = WARPS_M * WARPS_N * 32;
    constexpr int SAH  = BK + 8;     // A / BT-B row stride (halfs): 80 B rows
    constexpr int SBNH = BN + 8;     // non-BT B row stride (halfs)

    __shared__ __align__(16) __half As[BM * SAH];
    __shared__ __align__(16) __half Bs[BT ? (BN * SAH) : (BK * SBNH)];

    const int bh = blockIdx.z;
    A  += (size_t)bh * sA;
    Bp += (size_t)bh * sB;
    const int m0 = blockIdx.y * BM;
    const int n0 = blockIdx.x * BN;
    const int tid  = threadIdx.x;
    const int lane = tid & 31;
    const int warp = tid >> 5;
    const int wm = warp / WARPS_N;
    const int wn = warp % WARPS_N;
    const int gid = lane >> 2;      // 0..7
    const int tig = lane & 3;       // 0..3
    const int rr  = lane & 7;       // ldmatrix row within 8-group
    const int sub = lane >> 3;      // ldmatrix sub-matrix id 0..3

    float acc[4][4][4];
#pragma unroll
    for (int i = 0; i < 4; i++)
#pragma unroll
        for (int j = 0; j < 4; j++)
#pragma unroll
            for (int r = 0; r < 4; r++) acc[i][j][r] = 0.0f;

    for (int k0 = 0; k0 < K; k0 += BK) {
        // ---- A tile -> As[m][k] fp16 ----
#pragma unroll
        for (int t = 0; t < (BM * 8) / THREADS; t++) {
            int i  = tid + t * THREADS;
            int m  = i >> 3;
            int kq = i & 7;
            uint2 u = make_uint2(0u, 0u);
            if (m0 + m < M)
                u = ld4h(&A[(size_t)(m0 + m) * lda + k0 + kq * 4]);
            *(uint2*)&As[m * SAH + kq * 4] = u;
        }
        // ---- B tile ----
        if (BT) {   // B [N x K] -> Bs[n][k]
#pragma unroll
            for (int t = 0; t < (BN * 8) / THREADS; t++) {
                int i  = tid + t * THREADS;
                int n  = i >> 3;
                int kq = i & 7;
                uint2 u = ld4h(&Bp[(size_t)(n0 + n) * ldb + k0 + kq * 4]);
                *(uint2*)&Bs[n * SAH + kq * 4] = u;
            }
        } else {    // B [K x N] -> Bs[k][n]
#pragma unroll
            for (int t = 0; t < (BK * BN / 4) / THREADS; t++) {
                int i  = tid + t * THREADS;
                int kk = i / (BN / 4);
                int nq = i % (BN / 4);
                uint2 u = ld4h(&Bp[(size_t)(k0 + kk) * ldb + n0 + nq * 4]);
                *(uint2*)&Bs[kk * SBNH + nq * 4] = u;
            }
        }
        __syncthreads();

        // ---- compute: 2 x k16 steps per BK=32 ----
#pragma unroll
        for (int kk = 0; kk < BK; kk += 16) {
            unsigned af[4][4], bf[4][2];
            {
                int arow = rr + (sub & 1) * 8;
                int acol = kk + (sub >> 1) * 8;
#pragma unroll
                for (int i = 0; i < 4; i++) {
                    int row = wm * 64 + i * 16 + arow;
                    ldsm4h(af[i], &As[row * SAH + acol]);
                }
            }
            if (BT) {
                int brow = rr + (sub & 1) * 8;
                int bcol = kk + (sub >> 1) * 8;
#pragma unroll
                for (int jp = 0; jp < 2; jp++) {
                    int n = wn * 32 + jp * 16 + brow;
                    unsigned tmp[4];
                    ldsm4h(tmp, &Bs[n * SAH + bcol]);
                    bf[jp * 2][0]     = tmp[0];
                    bf[jp * 2][1]     = tmp[2];
                    bf[jp * 2 + 1][0] = tmp[1];
                    bf[jp * 2 + 1][1] = tmp[3];
                }
            } else {
                int krow = kk + (sub & 1) * 8 + rr;
#pragma unroll
                for (int jp = 0; jp < 2; jp++) {
                    int ncol = wn * 32 + jp * 16 + (sub >> 1) * 8;
                    unsigned tmp[4];
                    ldsm4h_t(tmp, &Bs[krow * SBNH + ncol]);
                    bf[jp * 2][0]     = tmp[0];
                    bf[jp * 2][1]     = tmp[1];
                    bf[jp * 2 + 1][0] = tmp[2];
                    bf[jp * 2 + 1][1] = tmp[3];
                }
            }
#pragma unroll
            for (int i = 0; i < 4; i++)
#pragma unroll
                for (int j = 0; j < 4; j++)
                    mma_f16(acc[i][j], af[i], bf[j]);
        }
        __syncthreads();
    }

    // ---- epilogue (N exact multiple of BN; only M ragged) ----
#pragma unroll
    for (int i = 0; i < 4; i++) {
        int rm = m0 + wm * 64 + i * 16 + gid;
#pragma unroll
        for (int j = 0; j < 4; j++) {
            int cn = n0 + wn * 32 + j * 8 + tig * 2;
            if (rm < M) {
                epi.store(bh, rm, cn,     acc[i][j][0]);
                epi.store(bh, rm, cn + 1, acc[i][j][1]);
            }
            if (rm + 8 < M) {
                epi.store(bh, rm + 8, cn,     acc[i][j][2]);
                epi.store(bh, rm + 8, cn + 1, acc[i][j][3]);
            }
        }
    }
}

// ---------------------------------------------------------------------------
// Small helper kernels (fp16 scratch aware)
// ---------------------------------------------------------------------------
__global__ void pool_kernel()
{
    int idx = blockIdx.x * blockDim.x + threadIdx.x;
    if (idx >= BH * Ll * Dd) return;
    int d  = idx % Dd;
    int l  = (idx / Dd) % Ll;
    int bh = idx / (Dd * Ll);
    int lr = l / 16, lc = l % 16;
    float sq = 0.f, sk = 0.f;
#pragma unroll
    for (int r = 0; r < 2; r++)
#pragma unroll
        for (int c = 0; c < 2; c++) {
            int p = (2 * lr + r) * 32 + (2 * lc + c);
            size_t off = ((size_t)bh * NT + (p + 1)) * Dd + d;
            sq += __half2float(g_q[off]);
            sk += __half2float(g_k[off]);
        }
    g_qland[((size_t)bh * Ll + l) * Dd + d] = __float2half_rn(sq * 0.25f);
    g_kland[((size_t)bh * Ll + l) * Dd + d] = __float2half_rn(sk * 0.25f);
}

__device__ __forceinline__ float row_sq_norm_h(const __half* p)
{
    const __half2* p2 = (const __half2*)p;
    float s = 0.f;
#pragma unroll
    for (int i = 0; i < Dd / 2; i++) {
        float2 v = __half22float2(p2[i]);
        s += v.x * v.x + v.y * v.y;
    }
    return s;
}

__global__ void norms_patch_kernel()
{
    int idx = blockIdx.x * blockDim.x + threadIdx.x;
    if (idx >= BH * NP) return;
    int bh = idx / NP, p = idx % NP;
    size_t off = ((size_t)bh * NT + (p + 1)) * Dd;
    g_qpn[idx] = row_sq_norm_h(&g_q[off]);
    g_kpn[idx] = row_sq_norm_h(&g_k[off]);
}

__global__ void norms_land_kernel()
{
    int idx = blockIdx.x * blockDim.x + threadIdx.x;
    if (idx >= BH * Ll) return;
    g_qln[idx] = row_sq_norm_h(&g_qland[(size_t)idx * Dd]);
    g_kln[idx] = row_sq_norm_h(&g_kland[(size_t)idx * Dd]);
    if (idx < BH)
        g_qcn[idx] = row_sq_norm_h(&g_q[(size_t)idx * NT * Dd]);  // n = 0 (cls)
}

__global__ void newton_init_kernel()
{
    int bh = blockIdx.x;
    int t  = threadIdx.x;
    const __half* M2b = g_M2 + (size_t)bh * Ll * Ll;
    const __half* row = M2b + (size_t)t * Ll;
    float rs = 0.f;
    for (int j = 0; j < Ll; j++) rs += fabsf(__half2float(row[j]));
    __shared__ float red[256];
    red[t] = rs;
    __syncthreads();
    for (int s = 128; s > 0; s >>= 1) {
        if (t < s) red[t] = fmaxf(red[t], red[t + s]);
        __syncthreads();
    }
    float nrm = red[0];
    float scale = 1.0f / (nrm * nrm + 1e-6f);
    __half* inv = g_invA + (size_t)bh * Ll * Ll;
    for (int idx = t; idx < Ll * Ll; idx += 256) {
        int i = idx / Ll, j = idx % Ll;
        inv[idx] = __float2half_rn(__half2float(M2b[(size_t)j * Ll + i]) * scale);
    }
}

__global__ void ycls_kernel()
{
    int bh = blockIdx.x;
    int t  = threadIdx.x;
    __shared__ float sc[Ll];
    __shared__ float qc[Dd];
    if (t < Dd) qc[t] = __half2float(g_q[(size_t)bh * NT * Dd + t]);
    __syncthreads();
    const __half* kl = g_kland + ((size_t)bh * Ll + t) * Dd;
    float dot = 0.f;
#pragma unroll
    for (int d = 0; d < Dd; d++) dot += qc[d] * __half2float(kl[d]);
    float dist = g_qcn[bh] + g_kln[(size_t)bh * Ll + t] - 2.0f * dot;
    sc[t] = fast_exp(dist * NEG_INV_TAU);
    __syncthreads();
    if (t < Dd) {
        float s = 0.f;
        for (int l = 0; l < Ll; l++)
            s += sc[l] * __half2float(g_Vmix[((size_t)bh * Ll + l) * Dd + t]);
        int b = bh / Hh, h = bh % Hh;
        g_attn[(size_t)b * NT * Cd + h * Dd + t] = __float2half_rn(s);
    }
}

// ---------------------------------------------------------------------------
// Host launcher
// ---------------------------------------------------------------------------
template<int BM, int BN, bool BT, class TA, class TB, class Epi>
static void launch_gemm(dim3 grid, const TA* A, const TB* Bp,
                        int M, int Nn, int K, int lda, int ldb,
                        size_t sA, size_t sB, Epi epi)
{
    constexpr int THREADS = (BM / 64) * (BN / 32) * 32;
    gemm_tc<BM, BN, BT, TA, TB, Epi><<<grid, THREADS>>>(
        A, Bp, M, Nn, K, lda, ldb, sA, sB, epi);
}

extern "C" void kernel_launch(void* const* d_in, const int* in_sizes, int n_in,
                              void* d_out, int out_size)
{
    (void)in_sizes; (void)n_in; (void)out_size;
    const float* x      = (const float*)d_in[0];
    const float* qkv_w  = (const float*)d_in[1];
    const float* qkv_b  = (const float*)d_in[2];
    const float* proj_w = (const float*)d_in[3];
    const float* proj_b = (const float*)d_in[4];
    float* out = (float*)d_out;

    __half *p_q, *p_k, *p_v, *p_qland, *p_kland;
    float *p_qpn, *p_kpn, *p_qln, *p_kln;
    __half *p_M1, *p_M2, *p_M3, *p_invA, *p_invB, *p_T, *p_KV, *p_Vmix, *p_attn;
    cudaGetSymbolAddress((void**)&p_q, g_q);
    cudaGetSymbolAddress((void**)&p_k, g_k);
    cudaGetSymbolAddress((void**)&p_v, g_v);
    cudaGetSymbolAddress((void**)&p_qland, g_qland);
    cudaGetSymbolAddress((void**)&p_kland, g_kland);
    cudaGetSymbolAddress((void**)&p_qpn, g_qpn);
    cudaGetSymbolAddress((void**)&p_kpn, g_kpn);
    cudaGetSymbolAddress((void**)&p_qln, g_qln);
    cudaGetSymbolAddress((void**)&p_kln, g_kln);
    cudaGetSymbolAddress((void**)&p_M1, g_M1);
    cudaGetSymbolAddress((void**)&p_M2, g_M2);
    cudaGetSymbolAddress((void**)&p_M3, g_M3);
    cudaGetSymbolAddress((void**)&p_invA, g_invA);
    cudaGetSymbolAddress((void**)&p_invB, g_invB);
    cudaGetSymbolAddress((void**)&p_T, g_T);
    cudaGetSymbolAddress((void**)&p_KV, g_KV);
    cudaGetSymbolAddress((void**)&p_Vmix, g_Vmix);
    cudaGetSymbolAddress((void**)&p_attn, g_attn);

    const int M_tok = Bn * NT;   // 16400
    const int gy_tok = (M_tok + 127) / 128;

    // 1. QKV projection (fp32 inputs)
    launch_gemm<128, 128, true>(dim3(3 * Cd / 128, gy_tok, 1),
        x, qkv_w, M_tok, 3 * Cd, Cd, Cd, Cd, (size_t)0, (size_t)0, EpiQKV{qkv_b});

    // 2. pooling + norms
    pool_kernel<<<(BH * Ll * Dd + 255) / 256, 256>>>();
    norms_patch_kernel<<<(BH * NP + 255) / 256, 256>>>();
    norms_land_kernel<<<(BH * Ll + 255) / 256, 256>>>();

    // 3. Gauss kernel matrices (fp16 in, fp16 out)
    launch_gemm<128, 128, true>(dim3(Ll / 128, Ll / 128, BH),       // M2
        p_qland, p_kland, Ll, Ll, Dd, Dd, Dd,
        (size_t)Ll * Dd, (size_t)Ll * Dd,
        EpiGauss{p_qln, p_kln, p_M2, Ll, Ll, Ll, (size_t)Ll * Ll});
    launch_gemm<128, 128, true>(dim3(Ll / 128, NP / 128, BH),       // M1
        p_q + Dd, p_kland, NP, Ll, Dd, Dd, Dd,
        (size_t)NT * Dd, (size_t)Ll * Dd,
        EpiGauss{p_qpn, p_kln, p_M1, NP, Ll, Ll, (size_t)NP * Ll});
    launch_gemm<128, 128, true>(dim3(NP / 128, Ll / 128, BH),       // M3
        p_qland, p_k + Dd, Ll, NP, Dd, Dd, Dd,
        (size_t)Ll * Dd, (size_t)NT * Dd,
        EpiGauss{p_qln, p_kpn, p_M3, Ll, NP, NP, (size_t)Ll * NP});

    // 4. Newton iterations for M2^-1 (all fp16 storage)
    newton_init_kernel<<<BH, 256>>>();
    {
        __half* cur = p_invA;
        __half* nxt = p_invB;
        dim3 grid(Ll / 128, Ll / 128, BH);
        for (int it = 0; it < NEWTON_ITERS; it++) {
            launch_gemm<128, 128, false>(grid,
                p_M2, (const __half*)cur, Ll, Ll, Ll, Ll, Ll,
                (size_t)Ll * Ll, (size_t)Ll * Ll,
                EpiPlainH{p_T, Ll, (size_t)Ll * Ll});
            launch_gemm<128, 128, false>(grid,
                (const __half*)cur, p_T, Ll, Ll, Ll, Ll, Ll,
                (size_t)Ll * Ll, (size_t)Ll * Ll,
                EpiNewton{cur, nxt});
            __half* tmp = cur; cur = nxt; nxt = tmp;
        }
        // NEWTON_ITERS even -> result in p_invA
    }

    // 5. KV = M3 @ v_patch : [L x D]
    launch_gemm<128, 64, false>(dim3(1, Ll / 128, BH),
        p_M3, p_v + Dd, Ll, Dd, NP, NP, Dd,
        (size_t)Ll * NP, (size_t)NT * Dd,
        EpiPlainH{p_KV, Dd, (size_t)Ll * Dd});
    // 6. V_mixed = M2_inv @ KV : [L x D]
    launch_gemm<128, 64, false>(dim3(1, Ll / 128, BH),
        (const __half*)p_invA, p_KV, Ll, Dd, Ll, Ll, Dd,
        (size_t)Ll * Ll, (size_t)Ll * Dd,
        EpiPlainH{p_Vmix, Dd, (size_t)Ll * Dd});
    // 7. y_patch = M1 @ V_mixed
    launch_gemm<128, 64, false>(dim3(1, NP / 128, BH),
        p_M1, p_Vmix, NP, Dd, Ll, Ll, Dd,
        (size_t)NP * Ll, (size_t)Ll * Dd, EpiYPatch{});
    // 8. y_cls
    ycls_kernel<<<BH, 256>>>();

    // 9. output projection (A fp16, B fp32, out fp32)
    launch_gemm<128, 128, true>(dim3(Cd / 128, gy_tok, 1),
        (const __half*)p_attn, proj_w, M_tok, Cd, Cd, Cd, Cd,
        (size_t)0, (size_t)0, EpiProj{proj_b, out});
}

// round 15
// speedup vs baseline: 2.3328x; 1.2101x over previous
#include <cuda_runtime.h>
#include <cuda_fp16.h>
#include <math.h>
#include <stddef.h>
#include <stdint.h>

// ---------------------------------------------------------------------------
// Problem constants
// ---------------------------------------------------------------------------
#define Bn   16
#define NT   1025            // tokens (1 cls + 1024 patches)
#define Cd   768
#define Hh   12
#define Dd   64
#define NP   1024            // patch tokens
#define Ll   256             // landmarks (16x16)
#define BH   (Bn*Hh)         // 192
#define NEWTON_ITERS 6
#define NEG_INV_TAU (-0.125f)   // tau = sqrt(64) = 8

// ---------------------------------------------------------------------------
// Scratch (static device globals) — intermediates in fp16, norms in fp32
// ---------------------------------------------------------------------------
__device__ __align__(16) __half g_q[BH * NT * Dd];
__device__ __align__(16) __half g_k[BH * NT * Dd];
__device__ __align__(16) __half g_v[BH * NT * Dd];
__device__ __align__(16) __half g_qland[BH * Ll * Dd];
__device__ __align__(16) __half g_kland[BH * Ll * Dd];
__device__ float g_qpn[BH * NP];
__device__ float g_kpn[BH * NP];
__device__ float g_qln[BH * Ll];
__device__ float g_kln[BH * Ll];
__device__ float g_qcn[BH];
__device__ __align__(16) __half g_M2[(size_t)BH * Ll * Ll];
__device__ __align__(16) __half g_invA[(size_t)BH * Ll * Ll];
__device__ __align__(16) __half g_invB[(size_t)BH * Ll * Ll];
__device__ __align__(16) __half g_T[(size_t)BH * Ll * Ll];
__device__ __align__(16) __half g_KV[BH * Ll * Dd];
__device__ __align__(16) __half g_Vmix[BH * Ll * Dd];
__device__ __align__(16) __half g_attn[(size_t)Bn * NT * Cd];

// ---------------------------------------------------------------------------
// Fast exp on FMA/ALU pipes (no MUFU).
// ---------------------------------------------------------------------------
__device__ __forceinline__ float fast_exp(float x)
{
    float y  = x * 1.4426950408889634f;       // log2(e)
    int   ni = __float2int_rn(y);
    float nf = (float)ni;
    float f  = y - nf;                        // [-0.5, 0.5]
    float p = 1.3333558146e-3f;
    p = fmaf(p, f, 9.6181291076e-3f);
    p = fmaf(p, f, 5.5504108664e-2f);
    p = fmaf(p, f, 2.4022650696e-1f);
    p = fmaf(p, f, 6.9314718056e-1f);
    p = fmaf(p, f, 1.0f);
    return __int_as_float(__float_as_int(p) + (ni << 23));
}

// ---------------------------------------------------------------------------
// Epilogue functors (batched GEMM)
// ---------------------------------------------------------------------------
struct EpiQKV {
    const float* bias;
    __device__ __forceinline__ void store(int, int m, int j, float acc) const {
        int b = m / NT, n = m % NT;
        int part = j / Cd;
        int rem  = j % Cd;
        int h = rem / Dd, d = rem % Dd;
        __half* dst = (part == 0) ? g_q : ((part == 1) ? g_k : g_v);
        dst[(((size_t)b * Hh + h) * NT + n) * Dd + d] = __float2half_rn(acc + bias[j]);
    }
};

struct EpiGauss {
    const float* xn; const float* yn; __half* out;
    int sxn; int syn; int ldc; size_t sout;
    __device__ __forceinline__ void store(int bh, int m, int n, float acc) const {
        float dist = xn[(size_t)bh * sxn + m] + yn[(size_t)bh * syn + n] - 2.0f * acc;
        out[(size_t)bh * sout + (size_t)m * ldc + n] =
            __float2half_rn(fast_exp(dist * NEG_INV_TAU));
    }
};

struct EpiPlainH {
    __half* out; int ldc; size_t s;
    __device__ __forceinline__ void store(int bh, int m, int n, float acc) const {
        out[(size_t)bh * s + (size_t)m * ldc + n] = __float2half_rn(acc);
    }
};

struct EpiNewton {   // out = 2*inv - acc
    const __half* inv; __half* out;
    __device__ __forceinline__ void store(int bh, int m, int n, float acc) const {
        size_t off = ((size_t)bh * Ll + m) * Ll + n;
        out[off] = __float2half_rn(2.0f * __half2float(inv[off]) - acc);
    }
};

struct EpiProj {
    const float* bias; float* out;
    __device__ __forceinline__ void store(int, int m, int j, float acc) const {
        out[(size_t)m * Cd + j] = acc + bias[j];
    }
};

// Fused-kernel output functors
struct OutKV {
    __device__ __forceinline__ void store(int bh, int row, int d, float v) const {
        g_KV[((size_t)bh * Ll + row) * Dd + d] = __float2half_rn(v);
    }
};
struct OutYP {
    __device__ __forceinline__ void store(int bh, int row, int d, float v) const {
        int b = bh / Hh, h = bh % Hh;
        g_attn[((size_t)b * NT + row + 1) * Cd + h * Dd + d] = __float2half_rn(v);
    }
};

// ---------------------------------------------------------------------------
// fp16 MMA helpers
// ---------------------------------------------------------------------------
__device__ __forceinline__ unsigned pack2h(float a, float b) {
    __half2 h = __floats2half2_rn(a, b);      // lo = a, hi = b
    return *(unsigned*)&h;
}

__device__ __forceinline__ uint2 ld4h(const float* p) {
    float4 v = *(const float4*)p;
    return make_uint2(pack2h(v.x, v.y), pack2h(v.z, v.w));
}
__device__ __forceinline__ uint2 ld4h(const __half* p) {
    return *(const uint2*)p;
}

__device__ __forceinline__ void mma_f16(float* c, const unsigned* a, const unsigned* b) {
    asm volatile(
        "mma.sync.aligned.m16n8k16.row.col.f32.f16.f16.f32 "
        "{%0,%1,%2,%3}, {%4,%5,%6,%7}, {%8,%9}, {%0,%1,%2,%3};"
        : "+f"(c[0]), "+f"(c[1]), "+f"(c[2]), "+f"(c[3])
        : "r"(a[0]), "r"(a[1]), "r"(a[2]), "r"(a[3]), "r"(b[0]), "r"(b[1]));
}

__device__ __forceinline__ void ldsm4h(unsigned* r, const __half* p) {
    unsigned a = (unsigned)__cvta_generic_to_shared((void*)p);
    asm volatile("ldmatrix.sync.aligned.m8n8.x4.shared.b16 {%0,%1,%2,%3}, [%4];"
                 : "=r"(r[0]), "=r"(r[1]), "=r"(r[2]), "=r"(r[3]) : "r"(a));
}

__device__ __forceinline__ void ldsm4h_t(unsigned* r, const __half* p) {
    unsigned a = (unsigned)__cvta_generic_to_shared((void*)p);
    asm volatile("ldmatrix.sync.aligned.m8n8.x4.trans.shared.b16 {%0,%1,%2,%3}, [%4];"
                 : "=r"(r[0]), "=r"(r[1]), "=r"(r[2]), "=r"(r[3]) : "r"(a));
}

// ---------------------------------------------------------------------------
// Fused gauss + AV kernel:
//   out[row, d] = sum_t  exp(-(xn[row] + yn[c] - 2 * A[row]·B[c]) / tau) * V[c, d]
// A block = 128 rows (rows contiguous, stride Dd). B/V tiles of 128 rows.
// Phase 1: S = A @ B^T (K=64) in two 128x64 n-halves -> exp -> P (smem fp16)
// Phase 2: accY += P @ V (K=128) via trans-ldsm.
// Warp geometry: 2x4 warps, 64x16 output tiles in both phases.
// ---------------------------------------------------------------------------
#define FUSED_SMEM (2 * 128 * 72 * 2 + 128 * 136 * 2)   // Aq + Bs + Ps = 71680 B

template<class Out>
__global__ void __launch_bounds__(256)
fused_gauss_av(const __half* __restrict__ Abase,
               const __half* __restrict__ Bbase,
               const __half* __restrict__ Vbase,
               const float* __restrict__ xn, const float* __restrict__ yn,
               int nxs, int nys,
               size_t sA, size_t sB, size_t sV,
               int ntiles, Out out)
{
    constexpr int SAH = 72;    // 64 + 8 halfs (144 B rows)
    constexpr int SPH = 136;   // 128 + 8 halfs (272 B rows)
    extern __shared__ __half fsm[];
    __half* Aq = fsm;                    // [128][72]
    __half* Bs = Aq + 128 * SAH;         // [128][72]  (K tile, then V tile)
    __half* Ps = Bs + 128 * SAH;         // [128][136]

    const int bh    = blockIdx.y;
    const int arow0 = blockIdx.x * 128;
    const int tid  = threadIdx.x;
    const int lane = tid & 31;
    const int warp = tid >> 5;
    const int wm = warp >> 2;            // 0..1
    const int wn = warp & 3;             // 0..3
    const int gid = lane >> 2;
    const int tig = lane & 3;
    const int rr  = lane & 7;
    const int sub = lane >> 3;

    const __half* Ag = Abase + (size_t)bh * sA + (size_t)arow0 * Dd;
    const __half* Bg = Bbase + (size_t)bh * sB;
    const __half* Vg = Vbase + (size_t)bh * sV;
    const float* xnb = xn + (size_t)bh * nxs + arow0;
    const float* ynb = yn + (size_t)bh * nys;

    // load A block once (128 x 64 halfs)
#pragma unroll
    for (int t = 0; t < 8; ++t) {
        int i = tid + t * 256;
        int r = i >> 4;
        int q = i & 15;
        *(uint2*)&Aq[r * SAH + q * 4] = *(const uint2*)&Ag[(size_t)r * Dd + q * 4];
    }

    float accY[4][2][4];
#pragma unroll
    for (int i = 0; i < 4; i++)
#pragma unroll
        for (int j = 0; j < 2; j++)
#pragma unroll
            for (int r = 0; r < 4; r++) accY[i][j][r] = 0.0f;

    for (int t = 0; t < ntiles; ++t) {
        __syncthreads();   // previous phase-2 reads of Bs done
        // ---- load K tile ----
#pragma unroll
        for (int u = 0; u < 8; ++u) {
            int i = tid + u * 256;
            int r = i >> 4, q = i & 15;
            *(uint2*)&Bs[r * SAH + q * 4] =
                *(const uint2*)&Bg[(size_t)(t * 128 + r) * Dd + q * 4];
        }
        __syncthreads();

        // ---- phase 1: S = A @ K^T in two 128x64 n-halves, exp -> Ps ----
#pragma unroll
        for (int nh = 0; nh < 2; ++nh) {
            float acc[4][2][4];
#pragma unroll
            for (int i = 0; i < 4; i++)
#pragma unroll
                for (int j = 0; j < 2; j++)
#pragma unroll
                    for (int r = 0; r < 4; r++) acc[i][j][r] = 0.0f;

#pragma unroll
            for (int kk = 0; kk < 64; kk += 16) {
                unsigned af[4][4], bf[2][2];
                int arow = rr + (sub & 1) * 8;
                int acol = kk + (sub >> 1) * 8;
#pragma unroll
                for (int i = 0; i < 4; i++)
                    ldsm4h(af[i], &Aq[(wm * 64 + i * 16 + arow) * SAH + acol]);
                int brow = nh * 64 + wn * 16 + rr + (sub & 1) * 8;
                int bcol = kk + (sub >> 1) * 8;
                unsigned tmp[4];
                ldsm4h(tmp, &Bs[brow * SAH + bcol]);
                bf[0][0] = tmp[0]; bf[0][1] = tmp[2];
                bf[1][0] = tmp[1]; bf[1][1] = tmp[3];
#pragma unroll
                for (int i = 0; i < 4; i++)
#pragma unroll
                    for (int j = 0; j < 2; j++)
                        mma_f16(acc[i][j], af[i], bf[j]);
            }
            // epilogue: gauss exp -> Ps
#pragma unroll
            for (int i = 0; i < 4; i++) {
                int rm = wm * 64 + i * 16 + gid;
                float xa = xnb[rm];
                float xb = xnb[rm + 8];
#pragma unroll
                for (int j = 0; j < 2; j++) {
                    int cn = nh * 64 + wn * 16 + j * 8 + tig * 2;
                    float y0 = ynb[t * 128 + cn];
                    float y1 = ynb[t * 128 + cn + 1];
                    float e0 = fast_exp((xa + y0 - 2.0f * acc[i][j][0]) * NEG_INV_TAU);
                    float e1 = fast_exp((xa + y1 - 2.0f * acc[i][j][1]) * NEG_INV_TAU);
                    float e2 = fast_exp((xb + y0 - 2.0f * acc[i][j][2]) * NEG_INV_TAU);
                    float e3 = fast_exp((xb + y1 - 2.0f * acc[i][j][3]) * NEG_INV_TAU);
                    *(__half2*)&Ps[rm * SPH + cn]       = __floats2half2_rn(e0, e1);
                    *(__half2*)&Ps[(rm + 8) * SPH + cn] = __floats2half2_rn(e2, e3);
                }
            }
        }
        __syncthreads();   // Bs reads done, Ps writes visible

        // ---- load V tile into Bs ----
#pragma unroll
        for (int u = 0; u < 8; ++u) {
            int i = tid + u * 256;
            int r = i >> 4, q = i & 15;
            *(uint2*)&Bs[r * SAH + q * 4] =
                *(const uint2*)&Vg[(size_t)(t * 128 + r) * Dd + q * 4];
        }
        __syncthreads();

        // ---- phase 2: accY += P @ V ----
#pragma unroll
        for (int kk = 0; kk < 128; kk += 16) {
            unsigned af[4][4], bf[2][2];
            int arow = rr + (sub & 1) * 8;
            int acol = kk + (sub >> 1) * 8;
#pragma unroll
            for (int i = 0; i < 4; i++)
                ldsm4h(af[i], &Ps[(wm * 64 + i * 16 + arow) * SPH + acol]);
            int krow = kk + (sub & 1) * 8 + rr;
            int ncol = wn * 16 + (sub >> 1) * 8;
            unsigned tmp[4];
            ldsm4h_t(tmp, &Bs[krow * SAH + ncol]);
            bf[0][0] = tmp[0]; bf[0][1] = tmp[1];
            bf[1][0] = tmp[2]; bf[1][1] = tmp[3];
#pragma unroll
            for (int i = 0; i < 4; i++)
#pragma unroll
                for (int j = 0; j < 2; j++)
                    mma_f16(accY[i][j], af[i], bf[j]);
        }
    }

    // ---- store accY ----
#pragma unroll
    for (int i = 0; i < 4; i++) {
        int rm = wm * 64 + i * 16 + gid;
#pragma unroll
        for (int j = 0; j < 2; j++) {
            int cn = wn * 16 + j * 8 + tig * 2;
            out.store(bh, arow0 + rm,     cn,     accY[i][j][0]);
            out.store(bh, arow0 + rm,     cn + 1, accY[i][j][1]);
            out.store(bh, arow0 + rm + 8, cn,     accY[i][j][2]);
            out.store(bh, arow0 + rm + 8, cn + 1, accY[i][j][3]);
        }
    }
}

// ---------------------------------------------------------------------------
// Synchronous fp16 tensor-core GEMM (R13, unchanged).
// ---------------------------------------------------------------------------
template<int BM, int BN, bool BT, class TA, class TB, class Epi>
__global__ void __launch_bounds__((BM / 64) * (BN / 32) * 32)
gemm_tc(const TA* __restrict__ A, const TB* __restrict__ Bp,
        int M, int Nn, int K, int lda, int ldb,
        size_t sA, size_t sB, Epi epi)
{
    constexpr int BK = 32;
    constexpr int WARPS_M = BM / 64;
    constexpr int WARPS_N = BN / 32;
    constexpr int THREADS = WARPS_M * WARPS_N * 32;
    constexpr int SAH  = BK + 8;
    constexpr int SBNH = BN + 8;

    __shared__ __align__(16) __half As[BM * SAH];
    __shared__ __align__(16) __half Bs[BT ? (BN * SAH) : (BK * SBNH)];

    const int bh = blockIdx.z;
    A  += (size_t)bh * sA;
    Bp += (size_t)bh * sB;
    const int m0 = blockIdx.y * BM;
    const int n0 = blockIdx.x * BN;
    const int tid  = threadIdx.x;
    const int lane = tid & 31;
    const int warp = tid >> 5;
    const int wm = warp / WARPS_N;
    const int wn = warp % WARPS_N;
    const int gid = lane >> 2;
    const int tig = lane & 3;
    const int rr  = lane & 7;
    const int sub = lane >> 3;

    float acc[4][4][4];
#pragma unroll
    for (int i = 0; i < 4; i++)
#pragma unroll
        for (int j = 0; j < 4; j++)
#pragma unroll
            for (int r = 0; r < 4; r++) acc[i][j][r] = 0.0f;

    for (int k0 = 0; k0 < K; k0 += BK) {
#pragma unroll
        for (int t = 0; t < (BM * 8) / THREADS; t++) {
            int i  = tid + t * THREADS;
            int m  = i >> 3;
            int kq = i & 7;
            uint2 u = make_uint2(0u, 0u);
            if (m0 + m < M)
                u = ld4h(&A[(size_t)(m0 + m) * lda + k0 + kq * 4]);
            *(uint2*)&As[m * SAH + kq * 4] = u;
        }
        if (BT) {
#pragma unroll
            for (int t = 0; t < (BN * 8) / THREADS; t++) {
                int i  = tid + t * THREADS;
                int n  = i >> 3;
                int kq = i & 7;
                uint2 u = ld4h(&Bp[(size_t)(n0 + n) * ldb + k0 + kq * 4]);
                *(uint2*)&Bs[n * SAH + kq * 4] = u;
            }
        } else {
#pragma unroll
            for (int t = 0; t < (BK * BN / 4) / THREADS; t++) {
                int i  = tid + t * THREADS;
                int kk = i / (BN / 4);
                int nq = i % (BN / 4);
                uint2 u = ld4h(&Bp[(size_t)(k0 + kk) * ldb + n0 + nq * 4]);
                *(uint2*)&Bs[kk * SBNH + nq * 4] = u;
            }
        }
        __syncthreads();

#pragma unroll
        for (int kk = 0; kk < BK; kk += 16) {
            unsigned af[4][4], bf[4][2];
            {
                int arow = rr + (sub & 1) * 8;
                int acol = kk + (sub >> 1) * 8;
#pragma unroll
                for (int i = 0; i < 4; i++) {
                    int row = wm * 64 + i * 16 + arow;
                    ldsm4h(af[i], &As[row * SAH + acol]);
                }
            }
            if (BT) {
                int brow = rr + (sub & 1) * 8;
                int bcol = kk + (sub >> 1) * 8;
#pragma unroll
                for (int jp = 0; jp < 2; jp++) {
                    int n = wn * 32 + jp * 16 + brow;
                    unsigned tmp[4];
                    ldsm4h(tmp, &Bs[n * SAH + bcol]);
                    bf[jp * 2][0]     = tmp[0];
                    bf[jp * 2][1]     = tmp[2];
                    bf[jp * 2 + 1][0] = tmp[1];
                    bf[jp * 2 + 1][1] = tmp[3];
                }
            } else {
                int krow = kk + (sub & 1) * 8 + rr;
#pragma unroll
                for (int jp = 0; jp < 2; jp++) {
                    int ncol = wn * 32 + jp * 16 + (sub >> 1) * 8;
                    unsigned tmp[4];
                    ldsm4h_t(tmp, &Bs[krow * SBNH + ncol]);
                    bf[jp * 2][0]     = tmp[0];
                    bf[jp * 2][1]     = tmp[1];
                    bf[jp * 2 + 1][0] = tmp[2];
                    bf[jp * 2 + 1][1] = tmp[3];
                }
            }
#pragma unroll
            for (int i = 0; i < 4; i++)
#pragma unroll
                for (int j = 0; j < 4; j++)
                    mma_f16(acc[i][j], af[i], bf[j]);
        }
        __syncthreads();
    }

#pragma unroll
    for (int i = 0; i < 4; i++) {
        int rm = m0 + wm * 64 + i * 16 + gid;
#pragma unroll
        for (int j = 0; j < 4; j++) {
            int cn = n0 + wn * 32 + j * 8 + tig * 2;
            if (rm < M) {
                epi.store(bh, rm, cn,     acc[i][j][0]);
                epi.store(bh, rm, cn + 1, acc[i][j][1]);
            }
            if (rm + 8 < M) {
                epi.store(bh, rm + 8, cn,     acc[i][j][2]);
                epi.store(bh, rm + 8, cn + 1, acc[i][j][3]);
            }
        }
    }
}

// ---------------------------------------------------------------------------
// Small helper kernels
// ---------------------------------------------------------------------------
__global__ void pool_kernel()
{
    int idx = blockIdx.x * blockDim.x + threadIdx.x;
    if (idx >= BH * Ll * Dd) return;
    int d  = idx % Dd;
    int l  = (idx / Dd) % Ll;
    int bh = idx / (Dd * Ll);
    int lr = l / 16, lc = l % 16;
    float sq = 0.f, sk = 0.f;
#pragma unroll
    for (int r = 0; r < 2; r++)
#pragma unroll
        for (int c = 0; c < 2; c++) {
            int p = (2 * lr + r) * 32 + (2 * lc + c);
            size_t off = ((size_t)bh * NT + (p + 1)) * Dd + d;
            sq += __half2float(g_q[off]);
            sk += __half2float(g_k[off]);
        }
    g_qland[((size_t)bh * Ll + l) * Dd + d] = __float2half_rn(sq * 0.25f);
    g_kland[((size_t)bh * Ll + l) * Dd + d] = __float2half_rn(sk * 0.25f);
}

__device__ __forceinline__ float row_sq_norm_h(const __half* p)
{
    const __half2* p2 = (const __half2*)p;
    float s = 0.f;
#pragma unroll
    for (int i = 0; i < Dd / 2; i++) {
        float2 v = __half22float2(p2[i]);
        s += v.x * v.x + v.y * v.y;
    }
    return s;
}

__global__ void norms_patch_kernel()
{
    int idx = blockIdx.x * blockDim.x + threadIdx.x;
    if (idx >= BH * NP) return;
    int bh = idx / NP, p = idx % NP;
    size_t off = ((size_t)bh * NT + (p + 1)) * Dd;
    g_qpn[idx] = row_sq_norm_h(&g_q[off]);
    g_kpn[idx] = row_sq_norm_h(&g_k[off]);
}

__global__ void norms_land_kernel()
{
    int idx = blockIdx.x * blockDim.x + threadIdx.x;
    if (idx >= BH * Ll) return;
    g_qln[idx] = row_sq_norm_h(&g_qland[(size_t)idx * Dd]);
    g_kln[idx] = row_sq_norm_h(&g_kland[(size_t)idx * Dd]);
    if (idx < BH)
        g_qcn[idx] = row_sq_norm_h(&g_q[(size_t)idx * NT * Dd]);  // n = 0 (cls)
}

__global__ void newton_init_kernel()
{
    int bh = blockIdx.x;
    int t  = threadIdx.x;
    const __half* M2b = g_M2 + (size_t)bh * Ll * Ll;
    const __half* row = M2b + (size_t)t * Ll;
    float rs = 0.f;
    for (int j = 0; j < Ll; j++) rs += fabsf(__half2float(row[j]));
    __shared__ float red[256];
    red[t] = rs;
    __syncthreads();
    for (int s = 128; s > 0; s >>= 1) {
        if (t < s) red[t] = fmaxf(red[t], red[t + s]);
        __syncthreads();
    }
    float nrm = red[0];
    float scale = 1.0f / (nrm * nrm + 1e-6f);
    __half* inv = g_invA + (size_t)bh * Ll * Ll;
    for (int idx = t; idx < Ll * Ll; idx += 256) {
        int i = idx / Ll, j = idx % Ll;
        inv[idx] = __float2half_rn(__half2float(M2b[(size_t)j * Ll + i]) * scale);
    }
}

__global__ void ycls_kernel()
{
    int bh = blockIdx.x;
    int t  = threadIdx.x;
    __shared__ float sc[Ll];
    __shared__ float qc[Dd];
    if (t < Dd) qc[t] = __half2float(g_q[(size_t)bh * NT * Dd + t]);
    __syncthreads();
    const __half* kl = g_kland + ((size_t)bh * Ll + t) * Dd;
    float dot = 0.f;
#pragma unroll
    for (int d = 0; d < Dd; d++) dot += qc[d] * __half2float(kl[d]);
    float dist = g_qcn[bh] + g_kln[(size_t)bh * Ll + t] - 2.0f * dot;
    sc[t] = fast_exp(dist * NEG_INV_TAU);
    __syncthreads();
    if (t < Dd) {
        float s = 0.f;
        for (int l = 0; l < Ll; l++)
            s += sc[l] * __half2float(g_Vmix[((size_t)bh * Ll + l) * Dd + t]);
        int b = bh / Hh, h = bh % Hh;
        g_attn[(size_t)b * NT * Cd + h * Dd + t] = __float2half_rn(s);
    }
}

// ---------------------------------------------------------------------------
// Host launchers
// ---------------------------------------------------------------------------
template<int BM, int BN, bool BT, class TA, class TB, class Epi>
static void launch_gemm(dim3 grid, const TA* A, const TB* Bp,
                        int M, int Nn, int K, int lda, int ldb,
                        size_t sA, size_t sB, Epi epi)
{
    constexpr int THREADS = (BM / 64) * (BN / 32) * 32;
    gemm_tc<BM, BN, BT, TA, TB, Epi><<<grid, THREADS>>>(
        A, Bp, M, Nn, K, lda, ldb, sA, sB, epi);
}

template<class Out>
static void launch_fused(dim3 grid, const __half* A, const __half* B, const __half* V,
                         const float* xn, const float* yn, int nxs, int nys,
                         size_t sA, size_t sB, size_t sV, int ntiles, Out out)
{
    static bool attr_done = false;
    if (!attr_done) {
        cudaFuncSetAttribute((const void*)fused_gauss_av<Out>,
                             cudaFuncAttributeMaxDynamicSharedMemorySize, FUSED_SMEM);
        attr_done = true;
    }
    fused_gauss_av<Out><<<grid, 256, FUSED_SMEM>>>(
        A, B, V, xn, yn, nxs, nys, sA, sB, sV, ntiles, out);
}

extern "C" void kernel_launch(void* const* d_in, const int* in_sizes, int n_in,
                              void* d_out, int out_size)
{
    (void)in_sizes; (void)n_in; (void)out_size;
    const float* x      = (const float*)d_in[0];
    const float* qkv_w  = (const float*)d_in[1];
    const float* qkv_b  = (const float*)d_in[2];
    const float* proj_w = (const float*)d_in[3];
    const float* proj_b = (const float*)d_in[4];
    float* out = (float*)d_out;

    __half *p_q, *p_k, *p_v, *p_qland, *p_kland;
    float *p_qpn, *p_kpn, *p_qln, *p_kln;
    __half *p_M2, *p_invA, *p_invB, *p_T, *p_KV, *p_Vmix, *p_attn;
    cudaGetSymbolAddress((void**)&p_q, g_q);
    cudaGetSymbolAddress((void**)&p_k, g_k);
    cudaGetSymbolAddress((void**)&p_v, g_v);
    cudaGetSymbolAddress((void**)&p_qland, g_qland);
    cudaGetSymbolAddress((void**)&p_kland, g_kland);
    cudaGetSymbolAddress((void**)&p_qpn, g_qpn);
    cudaGetSymbolAddress((void**)&p_kpn, g_kpn);
    cudaGetSymbolAddress((void**)&p_qln, g_qln);
    cudaGetSymbolAddress((void**)&p_kln, g_kln);
    cudaGetSymbolAddress((void**)&p_M2, g_M2);
    cudaGetSymbolAddress((void**)&p_invA, g_invA);
    cudaGetSymbolAddress((void**)&p_invB, g_invB);
    cudaGetSymbolAddress((void**)&p_T, g_T);
    cudaGetSymbolAddress((void**)&p_KV, g_KV);
    cudaGetSymbolAddress((void**)&p_Vmix, g_Vmix);
    cudaGetSymbolAddress((void**)&p_attn, g_attn);

    const int M_tok = Bn * NT;   // 16400
    const int gy_tok = (M_tok + 127) / 128;

    // 1. QKV projection (fp32 inputs)
    launch_gemm<128, 128, true>(dim3(3 * Cd / 128, gy_tok, 1),
        x, qkv_w, M_tok, 3 * Cd, Cd, Cd, Cd, (size_t)0, (size_t)0, EpiQKV{qkv_b});

    // 2. pooling + norms
    pool_kernel<<<(BH * Ll * Dd + 255) / 256, 256>>>();
    norms_patch_kernel<<<(BH * NP + 255) / 256, 256>>>();
    norms_land_kernel<<<(BH * Ll + 255) / 256, 256>>>();

    // 3. M2 gauss (needed for Newton)
    launch_gemm<128, 128, true>(dim3(Ll / 128, Ll / 128, BH),
        p_qland, p_kland, Ll, Ll, Dd, Dd, Dd,
        (size_t)Ll * Dd, (size_t)Ll * Dd,
        EpiGauss{p_qln, p_kln, p_M2, Ll, Ll, Ll, (size_t)Ll * Ll});

    // 4. fused M3+KV: KV = gauss(q_land, k_patch) @ v_patch
    launch_fused(dim3(2, BH), p_qland, p_k + Dd, p_v + Dd,
                 p_qln, p_kpn, Ll, NP,
                 (size_t)Ll * Dd, (size_t)NT * Dd, (size_t)NT * Dd, NP / 128, OutKV{});

    // 5. Newton iterations for M2^-1
    newton_init_kernel<<<BH, 256>>>();
    {
        __half* cur = p_invA;
        __half* nxt = p_invB;
        dim3 grid(Ll / 128, Ll / 128, BH);
        for (int it = 0; it < NEWTON_ITERS; it++) {
            launch_gemm<128, 128, false>(grid,
                p_M2, (const __half*)cur, Ll, Ll, Ll, Ll, Ll,
                (size_t)Ll * Ll, (size_t)Ll * Ll,
                EpiPlainH{p_T, Ll, (size_t)Ll * Ll});
            launch_gemm<128, 128, false>(grid,
                (const __half*)cur, p_T, Ll, Ll, Ll, Ll, Ll,
                (size_t)Ll * Ll, (size_t)Ll * Ll,
                EpiNewton{cur, nxt});
            __half* tmp = cur; cur = nxt; nxt = tmp;
        }
        // NEWTON_ITERS even -> result in p_invA
    }

    // 6. V_mixed = M2_inv @ KV : [L x D]
    launch_gemm<128, 64, false>(dim3(1, Ll / 128, BH),
        (const __half*)p_invA, p_KV, Ll, Dd, Ll, Ll, Dd,
        (size_t)Ll * Ll, (size_t)Ll * Dd,
        EpiPlainH{p_Vmix, Dd, (size_t)Ll * Dd});

    // 7. fused M1+y_patch: attn_patch = gauss(q_patch, k_land) @ V_mixed
    launch_fused(dim3(NP / 128, BH), p_q + Dd, p_kland, p_Vmix,
                 p_qpn, p_kln, NP, Ll,
                 (size_t)NT * Dd, (size_t)Ll * Dd, (size_t)Ll * Dd, Ll / 128, OutYP{});

    // 8. y_cls
    ycls_kernel<<<BH, 256>>>();

    // 9. output projection (A fp16, B fp32, out fp32)
    launch_gemm<128, 128, true>(dim3(Cd / 128, gy_tok, 1),
        (const __half*)p_attn, proj_w, M_tok, Cd, Cd, Cd, Cd,
        (size_t)0, (size_t)0, EpiProj{proj_b, out});
}